// round 14
// baseline (speedup 1.0000x reference)
#include <cuda_runtime.h>
#include <cuda_fp16.h>
#include <cstddef>

typedef unsigned long long ull;
typedef unsigned int uint;

// ---------------- problem constants (shapes fixed by the dataset) -----------
#define MAXN 100000
#define MAXE 1600000
#define MAXET (MAXE + MAXN)
#define MAXETP (MAXET + 16)   // padded: slot MAXET is a never-written zero row
#define NBM  ((MAXN + 31) / 32)
#define FN   128     // node feature dim (layer1 input)
#define FE   32      // edge feature dim
#define HID  64

// ---------------- device scratch (static: no allocation allowed) ------------
__device__ __align__(16) __half g_xlh[MAXN * HID];  // source-side transform (fp16)
__device__ __align__(16) __half g_xrh[MAXN * HID];  // target-side transform (fp16)
__device__ float  g_out [MAXN * HID];       // layer output (valid at T1 nodes)
__device__ int    g_degc[MAXN];             // degree per T1 index (zero at entry)
__device__ int    g_mark1[MAXN];            // T1 index+1 (valid only where bm1 set)
__device__ uint   g_bm1 [NBM];              // T1 bitmask (zeroed by fin)
__device__ uint   g_bm2 [NBM];              // T2 bitmask (zeroed by fin)
__device__ int    g_rowptr[MAXN + 1];       // compact rowptr over T1 indices
__device__ int    g_cur [MAXN];
__device__ int    g_csr_src[MAXETP];        // src node per compact slot
__device__ int    g_list1[MAXN];            // compacted T1 node list
__device__ int    g_list2[MAXN];            // compacted T2 node list
__device__ int2   g_pair_es[MAXET];         // (eid, src) of accepted edges
__device__ int2   g_pair_md[MAXET];         // (T1 idx, dst) of accepted edges
__device__ int    g_n1, g_n2, g_np;         // zero at entry (fin restores)
__device__ __align__(16) __half g_eap[(size_t)MAXETP * FE];  // permuted fp16 edge attrs

// ---------------- small helpers ---------------------------------------------
__device__ __forceinline__ void mma_f16(float acc[4], uint a0, uint a1, uint a2, uint a3,
                                        uint b0, uint b1) {
    asm volatile(
        "mma.sync.aligned.m16n8k16.row.col.f32.f16.f16.f32 "
        "{%0,%1,%2,%3}, {%4,%5,%6,%7}, {%8,%9}, {%0,%1,%2,%3};"
        : "+f"(acc[0]), "+f"(acc[1]), "+f"(acc[2]), "+f"(acc[3])
        : "r"(a0), "r"(a1), "r"(a2), "r"(a3), "r"(b0), "r"(b1));
}
__device__ __forceinline__ float2 h2f2(uint v) {
    __half2 h = *reinterpret_cast<__half2*>(&v);
    return __half22float2(h);
}
__device__ __forceinline__ uint f2h2(float x, float y) {
    __half2 h = __floats2half2_rn(x, y);
    return *reinterpret_cast<uint*>(&h);
}
__device__ __forceinline__ bool bm_test(const uint* bm, int i) {
    return (bm[i >> 5] >> (i & 31)) & 1u;
}

// ================= active-set construction ===================================
__global__ void mark2_kernel(const int* __restrict__ nidx, int M) {
    int m = blockIdx.x * blockDim.x + threadIdx.x;
    if (m >= M) return;
    int d = nidx[m];
    uint bit = 1u << (d & 31);
    if (!(atomicOr(&g_bm2[d >> 5], bit) & bit)) {
        int p = atomicAdd(&g_n2, 1); g_list2[p] = d;
    }
    if (!(atomicOr(&g_bm1[d >> 5], bit) & bit)) {
        int p = atomicAdd(&g_n1, 1); g_list1[p] = d; g_mark1[d] = p + 1;
    }
}

// T1 += sources of edges whose dst is in T2 (bit probe, L1-resident bitmask)
__global__ void markS_kernel(const int* __restrict__ ei, int E) {
    int i = blockIdx.x * blockDim.x + threadIdx.x;
    if (i >= E) return;
    int d = ei[E + i];
    if (bm_test(g_bm2, d)) {
        int s = ei[i];
        uint bit = 1u << (s & 31);
        if (!(atomicOr(&g_bm1[s >> 5], bit) & bit)) {
            int p = atomicAdd(&g_n1, 1); g_list1[p] = s; g_mark1[s] = p + 1;
        }
    }
}

// ================= compact CSR build (T1 segments only) =======================
// Single E-scan: bit probe, then index lookup only for accepted edges.
__global__ void collect_kernel(const int* __restrict__ ei, int E) {
    int i = blockIdx.x * blockDim.x + threadIdx.x;
    if (i >= E) return;
    int d = ei[E + i];
    if (!bm_test(g_bm1, d)) return;
    int m = g_mark1[d] - 1;
    int j = atomicAdd(&g_np, 1);
    g_pair_es[j] = make_int2(i, ei[i]);
    g_pair_md[j] = make_int2(m, d);
    atomicAdd(&g_degc[m], 1);
}

// single-block prefix scan over T1 indices: rowptr/cursors from (deg+1)
__global__ __launch_bounds__(1024) void scan_kernel() {
    __shared__ int wsum[32];
    __shared__ int s_carry;
    const int n1 = g_n1;
    const int tid = threadIdx.x;
    const int lane = tid & 31, wid = tid >> 5;
    if (tid == 0) s_carry = 0;
    __syncthreads();
    const int CH = 8;
    for (int base = 0; base < n1; base += 1024 * CH) {
        int idx0 = base + tid * CH;
        int vals[CH];
        int sum = 0;
        #pragma unroll
        for (int j = 0; j < CH; ++j) {
            int ix = idx0 + j;
            int v = (ix < n1) ? (g_degc[ix] + 1) : 0;
            vals[j] = sum;
            sum += v;
        }
        int s = sum;
        #pragma unroll
        for (int off = 1; off < 32; off <<= 1) {
            int t = __shfl_up_sync(0xffffffffu, s, off);
            if (lane >= off) s += t;
        }
        if (lane == 31) wsum[wid] = s;
        __syncthreads();
        if (wid == 0) {
            int ws = wsum[lane];
            #pragma unroll
            for (int off = 1; off < 32; off <<= 1) {
                int t = __shfl_up_sync(0xffffffffu, ws, off);
                if (lane >= off) ws += t;
            }
            wsum[lane] = ws;
        }
        __syncthreads();
        int thread_excl = (s - sum) + (wid ? wsum[wid - 1] : 0);
        int carry = s_carry;
        #pragma unroll
        for (int j = 0; j < CH; ++j) {
            int ix = idx0 + j;
            if (ix < n1) {
                int rp = carry + thread_excl + vals[j];
                g_rowptr[ix] = rp;
                g_cur[ix]    = rp;
            }
        }
        __syncthreads();
        if (tid == 0) s_carry = carry + wsum[31];
        __syncthreads();
    }
    if (tid == 0) g_rowptr[n1] = s_carry;
}

// place accepted edges into compact slots + permute/convert edge attrs
__global__ void place_kernel(const float* __restrict__ ea) {
    const int np = g_np;
    const int stride = gridDim.x * blockDim.x;
    for (int j = blockIdx.x * blockDim.x + threadIdx.x; j < np; j += stride) {
        int2 es = g_pair_es[j];
        int2 md = g_pair_md[j];
        int pos = atomicAdd(&g_cur[md.x], 1);
        g_csr_src[pos] = es.y;
        const float4* r4 = reinterpret_cast<const float4*>(ea) + (size_t)es.x * 8;
        __half2* dst = reinterpret_cast<__half2*>(g_eap + (size_t)pos * FE);
        #pragma unroll
        for (int q = 0; q < 8; ++q) {
            float4 v = r4[q];
            dst[2 * q]     = __floats2half2_rn(v.x, v.y);
            dst[2 * q + 1] = __floats2half2_rn(v.z, v.w);
        }
    }
}

// self-loop mean per T1 segment (fills last slot of each segment)
__global__ void prep_kernel() {
    const int lane = threadIdx.x & 31;
    const int gws = gridDim.x * 8;
    const int n1 = g_n1;
    for (int widx = blockIdx.x * 8 + (threadIdx.x >> 5); widx < n1; widx += gws) {
        const int d = g_list1[widx];
        const int rp0 = g_rowptr[widx], rp1 = g_rowptr[widx + 1];
        const int last = rp1 - 1;            // self-loop slot
        float s = 0.f;
        int e = rp0;
        for (; e + 4 <= last; e += 4) {
            float a0 = __half2float(g_eap[(size_t)(e + 0) * FE + lane]);
            float a1 = __half2float(g_eap[(size_t)(e + 1) * FE + lane]);
            float a2 = __half2float(g_eap[(size_t)(e + 2) * FE + lane]);
            float a3 = __half2float(g_eap[(size_t)(e + 3) * FE + lane]);
            s += (a0 + a1) + (a2 + a3);
        }
        for (; e < last; ++e) s += __half2float(g_eap[(size_t)e * FE + lane]);
        float mean = s / (float)max(last - rp0, 1);
        g_eap[(size_t)last * FE + lane] = __float2half_rn(mean);
        if (lane == 0) g_csr_src[last] = d;
    }
}

// ---------------- single-output node linear via fp16 tensor MMA --------------
template<int IN, int SET, bool HPREV>
__global__ __launch_bounds__(256) void lin_f16_kernel(
        const float* __restrict__ inp, const float* __restrict__ W,
        const float* __restrict__ bias, const float* __restrict__ prevBias,
        int N, int right) {
    const int nlim = (SET == 0) ? N : (SET == 1 ? g_n1 : g_n2);
    const int nb = blockIdx.x * 128;
    if (nb >= nlim) return;

    constexpr int KC = 16;                    // k per iteration (one k16 MMA step)
    __shared__ uint Xs[128][9];               // 8 k-pair words + pad
    __shared__ uint Ws[8][68];                // k-pair word x 64 cols + pad

    const int t = threadIdx.x;
    const int lane = t & 31;
    const int mt = t >> 5;                    // warp = m-tile 0..7
    const int g = lane >> 2, c = lane & 3;

    float acc[8][4];
    #pragma unroll
    for (int nt = 0; nt < 8; ++nt) {
        acc[nt][0] = acc[nt][1] = acc[nt][2] = acc[nt][3] = 0.f;
    }

    for (int kc = 0; kc < IN; kc += KC) {
        __syncthreads();
        for (int idx = t; idx < 128 * 8; idx += 256) {
            int row = idx >> 3, kw = idx & 7;
            int m = nb + row;
            float v0 = 0.f, v1 = 0.f;
            if (m < nlim) {
                int node = (SET == 0) ? m : (SET == 1 ? g_list1[m] : g_list2[m]);
                int j = kc + 2 * kw;
                if (HPREV) {
                    float2 hv = *reinterpret_cast<const float2*>(g_out + (size_t)node * HID + j);
                    v0 = fmaxf(hv.x + prevBias[j], 0.f);
                    v1 = fmaxf(hv.y + prevBias[j + 1], 0.f);
                } else {
                    float2 xv = *reinterpret_cast<const float2*>(inp + (size_t)node * IN + j);
                    v0 = xv.x; v1 = xv.y;
                }
            }
            Xs[row][kw] = f2h2(v0, v1);
        }
        for (int idx = t; idx < 8 * 64; idx += 256) {
            int kw = idx >> 6, col = idx & 63;
            int k = kc + 2 * kw;
            Ws[kw][col] = f2h2(W[k * HID + col], W[(k + 1) * HID + col]);
        }
        __syncthreads();
        uint a0 = Xs[mt * 16 + g    ][c];
        uint a1 = Xs[mt * 16 + g + 8][c];
        uint a2 = Xs[mt * 16 + g    ][c + 4];
        uint a3 = Xs[mt * 16 + g + 8][c + 4];
        #pragma unroll
        for (int nt = 0; nt < 8; ++nt) {
            int col = nt * 8 + g;
            mma_f16(acc[nt], a0, a1, a2, a3, Ws[c][col], Ws[c + 4][col]);
        }
    }

    uint* dsth = reinterpret_cast<uint*>(right ? g_xrh : g_xlh);
    const int m0 = nb + mt * 16 + g;
    const int m1 = m0 + 8;
    const int node0 = (m0 < nlim) ? ((SET == 0) ? m0 : (SET == 1 ? g_list1[m0] : g_list2[m0])) : -1;
    const int node1 = (m1 < nlim) ? ((SET == 0) ? m1 : (SET == 1 ? g_list1[m1] : g_list2[m1])) : -1;
    #pragma unroll
    for (int nt = 0; nt < 8; ++nt) {
        int colL = nt * 8 + 2 * c;
        float bx = bias[colL], by = bias[colL + 1];
        if (node0 >= 0)
            dsth[(size_t)node0 * 32 + nt * 4 + c] = f2h2(acc[nt][0] + bx, acc[nt][1] + by);
        if (node1 >= 0)
            dsth[(size_t)node1 * 32 + nt * 4 + c] = f2h2(acc[nt][2] + bx, acc[nt][3] + by);
    }
}

// ---------------- fused edge pass: warp-per-segment GATv2 --------------------
__global__ __launch_bounds__(256) void edge_fused_kernel(
        const float* __restrict__ We, const float* __restrict__ att, int layer) {
    const int n = (layer == 1) ? g_n1 : g_n2;
    const int t = threadIdx.x;
    const int lane = t & 31;
    const int g = lane >> 2;                 // row group 0..7
    const int c = lane & 3;                  // col-in-group 0..3
    const int gws = gridDim.x * 8;

    // preload B fragments (We as fp16) and att pairs into registers
    uint breg[8][2][2];
    float2 areg[8];
    #pragma unroll
    for (int nt = 0; nt < 8; ++nt) {
        const int nn = nt * 8 + g;
        #pragma unroll
        for (int ks = 0; ks < 2; ++ks) {
            int k0 = ks * 16 + 2 * c;
            breg[nt][ks][0] = f2h2(We[k0 * HID + nn],       We[(k0 + 1) * HID + nn]);
            breg[nt][ks][1] = f2h2(We[(k0 + 8) * HID + nn], We[(k0 + 9) * HID + nn]);
        }
        areg[nt] = reinterpret_cast<const float2*>(att)[nt * 4 + c];
    }

    const uint* xlh = reinterpret_cast<const uint*>(g_xlh);
    const uint* xrh = reinterpret_cast<const uint*>(g_xrh);

    for (int widx = blockIdx.x * 8 + (t >> 5); widx < n; widx += gws) {
        int d, m;
        if (layer == 1) { d = g_list1[widx]; m = widx; }
        else            { d = g_list2[widx]; m = g_mark1[d] - 1; }
        const int rp0 = g_rowptr[m], rp1 = g_rowptr[m + 1];

        // xr[d] loaded once per segment
        float2 xr[8];
        #pragma unroll
        for (int nt = 0; nt < 8; ++nt)
            xr[nt] = h2f2(xrh[(size_t)d * 32 + nt * 4 + c]);

        float den = 0.f;
        float2 o[8];
        #pragma unroll
        for (int nt = 0; nt < 8; ++nt) o[nt] = make_float2(0.f, 0.f);

        for (int base = rp0; base < rp1; base += 16) {
            const int rowA = base + g;
            const int rowB = rowA + 8;
            const bool vA = rowA < rp1, vB = rowB < rp1;
            const int slotA = vA ? rowA : MAXET;   // pad slot: zeros
            const int slotB = vB ? rowB : MAXET;
            const int sA = g_csr_src[slotA], sB = g_csr_src[slotB];
            const uint* pA = reinterpret_cast<const uint*>(g_eap + (size_t)slotA * FE);
            const uint* pB = reinterpret_cast<const uint*>(g_eap + (size_t)slotB * FE);

            uint afr[2][4];
            #pragma unroll
            for (int ks = 0; ks < 2; ++ks) {
                afr[ks][0] = pA[ks * 8 + c];
                afr[ks][1] = pB[ks * 8 + c];
                afr[ks][2] = pA[ks * 8 + c + 4];
                afr[ks][3] = pB[ks * 8 + c + 4];
            }

            float2 xlA[8], xlB[8];
            float partA = 0.f, partB = 0.f;
            #pragma unroll
            for (int nt = 0; nt < 8; ++nt) {
                float acc[4] = {0.f, 0.f, 0.f, 0.f};
                mma_f16(acc, afr[0][0], afr[0][1], afr[0][2], afr[0][3],
                        breg[nt][0][0], breg[nt][0][1]);
                mma_f16(acc, afr[1][0], afr[1][1], afr[1][2], afr[1][3],
                        breg[nt][1][0], breg[nt][1][1]);
                xlA[nt] = h2f2(xlh[(size_t)sA * 32 + nt * 4 + c]);
                xlB[nt] = h2f2(xlh[(size_t)sB * 32 + nt * 4 + c]);
                float u0 = acc[0] + xlA[nt].x + xr[nt].x;
                float u1 = acc[1] + xlA[nt].y + xr[nt].y;
                float u2 = acc[2] + xlB[nt].x + xr[nt].x;
                float u3 = acc[3] + xlB[nt].y + xr[nt].y;
                u0 = fmaxf(u0, 0.f) + 0.2f * fminf(u0, 0.f);
                u1 = fmaxf(u1, 0.f) + 0.2f * fminf(u1, 0.f);
                u2 = fmaxf(u2, 0.f) + 0.2f * fminf(u2, 0.f);
                u3 = fmaxf(u3, 0.f) + 0.2f * fminf(u3, 0.f);
                partA = fmaf(u0, areg[nt].x, fmaf(u1, areg[nt].y, partA));
                partB = fmaf(u2, areg[nt].x, fmaf(u3, areg[nt].y, partB));
            }
            partA += __shfl_xor_sync(0xffffffffu, partA, 1);
            partA += __shfl_xor_sync(0xffffffffu, partA, 2);
            partB += __shfl_xor_sync(0xffffffffu, partB, 1);
            partB += __shfl_xor_sync(0xffffffffu, partB, 2);
            const float eA = vA ? __expf(partA) : 0.f;
            const float eB = vB ? __expf(partB) : 0.f;
            den += eA + eB;
            #pragma unroll
            for (int nt = 0; nt < 8; ++nt) {
                o[nt].x = fmaf(eA, xlA[nt].x, fmaf(eB, xlB[nt].x, o[nt].x));
                o[nt].y = fmaf(eA, xlA[nt].y, fmaf(eB, xlB[nt].y, o[nt].y));
            }
        }

        // reduce across the 8 row-groups (lane = g*4 + c)
        #pragma unroll
        for (int off = 4; off <= 16; off <<= 1) {
            den += __shfl_xor_sync(0xffffffffu, den, off);
            #pragma unroll
            for (int nt = 0; nt < 8; ++nt) {
                o[nt].x += __shfl_xor_sync(0xffffffffu, o[nt].x, off);
                o[nt].y += __shfl_xor_sync(0xffffffffu, o[nt].y, off);
            }
        }
        const float inv = 1.f / den;
        if (g == 0) {
            float2* out2 = reinterpret_cast<float2*>(g_out);
            #pragma unroll
            for (int nt = 0; nt < 8; ++nt)
                out2[(size_t)d * 32 + nt * 4 + c] = make_float2(o[nt].x * inv, o[nt].y * inv);
        }
    }
}

// ---------------- final MLP at node_idx + restore zero-invariants ------------
__global__ void fin_kernel(const int* __restrict__ idx, const float* __restrict__ bias2,
                           const float* __restrict__ y,
                           const float* __restrict__ W0, const float* __restrict__ b0,
                           const float* __restrict__ W1, const float* __restrict__ b1,
                           const float* __restrict__ W2, const float* __restrict__ b2,
                           float* __restrict__ dout, int M, int rf, int N) {
    // restore zero-invariants for the next launch (graph replay safe)
    int tid = blockIdx.x * blockDim.x + threadIdx.x;
    for (int z = tid; z < N; z += gridDim.x * blockDim.x) g_degc[z] = 0;
    for (int z = tid; z < NBM; z += gridDim.x * blockDim.x) { g_bm1[z] = 0u; g_bm2[z] = 0u; }
    if (tid == 0) { g_n1 = 0; g_n2 = 0; g_np = 0; }

    __shared__ float sh[4][64];
    __shared__ float sz[4][32];
    const int w = threadIdx.x >> 5, lane = threadIdx.x & 31;
    const int m = blockIdx.x * 4 + w;
    if (m >= M) return;
    const int v = idx[m];

    float h0 = fmaxf(g_out[(size_t)v * HID + lane]      + bias2[lane],      0.f);
    float h1 = fmaxf(g_out[(size_t)v * HID + 32 + lane] + bias2[32 + lane], 0.f);
    sh[w][lane] = h0; sh[w][32 + lane] = h1;
    __syncwarp();

    int k = v / rf;
    float y0 = y[2 * k], y1 = y[2 * k + 1];
    float q0 = fmaxf(y0 * W0[0] + y1 * W0[2] + b0[0], 0.f);
    float q1 = fmaxf(y0 * W0[1] + y1 * W0[3] + b0[1], 0.f);

    float z = b1[lane];
    #pragma unroll
    for (int j = 0; j < 64; ++j) z += sh[w][j] * W1[j * 32 + lane];
    z += q0 * W1[64 * 32 + lane] + q1 * W1[65 * 32 + lane];
    z = fmaxf(z, 0.f);
    sz[w][lane] = z;
    __syncwarp();

    float o = b2[lane];
    #pragma unroll
    for (int j = 0; j < 32; ++j) o += sz[w][j] * W2[j * 32 + lane];
    dout[m * 32 + lane] = o;
}

// ---------------- launch ------------------------------------------------------
extern "C" void kernel_launch(void* const* d_in, const int* in_sizes, int n_in,
                              void* d_out, int out_size) {
    const float* x    = (const float*)d_in[0];
    const float* ea   = (const float*)d_in[1];
    const float* y    = (const float*)d_in[2];
    const float* Wl1  = (const float*)d_in[3];
    const float* bl1  = (const float*)d_in[4];
    const float* Wr1  = (const float*)d_in[5];
    const float* br1  = (const float*)d_in[6];
    const float* We1  = (const float*)d_in[7];
    const float* att1 = (const float*)d_in[8];
    const float* bias1= (const float*)d_in[9];
    const float* Wl2  = (const float*)d_in[10];
    const float* bl2  = (const float*)d_in[11];
    const float* Wr2  = (const float*)d_in[12];
    const float* br2  = (const float*)d_in[13];
    const float* We2  = (const float*)d_in[14];
    const float* att2 = (const float*)d_in[15];
    const float* bias2= (const float*)d_in[16];
    const float* W0   = (const float*)d_in[17];
    const float* b0   = (const float*)d_in[18];
    const float* W1   = (const float*)d_in[19];
    const float* b1   = (const float*)d_in[20];
    const float* W2   = (const float*)d_in[21];
    const float* b2   = (const float*)d_in[22];
    const int*   ei   = (const int*)  d_in[23];
    const int*   nidx = (const int*)  d_in[24];

    const int N    = in_sizes[0] / FN;
    const int E    = in_sizes[23] / 2;
    const int M    = in_sizes[24];
    const int NG   = in_sizes[2] / 2;
    const int rf   = N / NG;

    const int EBLK = (E + 255) / 256;
    const int LINB = (N + 127) / 128;

    // ---- active sets (bitmask probes) ----
    mark2_kernel   <<<(M + 255) / 256, 256>>>(nidx, M);
    markS_kernel   <<<EBLK, 256>>>(ei, E);

    // ---- compact CSR over T1 (one E-scan + single-block scan) ----
    collect_kernel <<<EBLK, 256>>>(ei, E);
    scan_kernel    <<<1, 1024>>>();
    place_kernel   <<<1024, 256>>>(ea);
    prep_kernel    <<<512, 256>>>();

    // ---- layer 1: xl over all N, xr over T1; fused edge pass over T1 ----
    lin_f16_kernel<FN, 0, false><<<LINB, 256>>>(x, Wl1, bl1, nullptr, N, 0);
    lin_f16_kernel<FN, 1, false><<<LINB, 256>>>(x, Wr1, br1, nullptr, N, 1);
    edge_fused_kernel<<<1024, 256>>>(We1, att1, 1);

    // ---- layer 2: xl over T1, xr over T2; fused edge pass over T2 ----
    lin_f16_kernel<HID, 1, true><<<LINB, 256>>>(x, Wl2, bl2, bias1, N, 0);
    lin_f16_kernel<HID, 2, true><<<LINB, 256>>>(x, Wr2, br2, bias1, N, 1);
    edge_fused_kernel<<<128, 256>>>(We2, att2, 2);

    // ---- final MLP at node_idx (also restores zero-invariants) ----
    fin_kernel<<<512, 128>>>(nidx, bias2, y, W0, b0, W1, b1, W2, b2,
                             (float*)d_out, M, rf, N);
}

// round 15
// speedup vs baseline: 1.0503x; 1.0503x over previous
#include <cuda_runtime.h>
#include <cuda_fp16.h>
#include <cstddef>

typedef unsigned long long ull;
typedef unsigned int uint;

// ---------------- problem constants (shapes fixed by the dataset) -----------
#define MAXN 100000
#define MAXE 1600000
#define MAXET (MAXE + MAXN)
#define MAXETP (MAXET + 16)   // padded: slot MAXET is a never-written zero row
#define NBM  ((MAXN + 31) / 32)
#define FN   128     // node feature dim (layer1 input)
#define FE   32      // edge feature dim
#define HID  64

// ---------------- device scratch (static: no allocation allowed) ------------
__device__ __align__(16) __half g_xlh[MAXN * HID];  // source-side transform (fp16)
__device__ __align__(16) __half g_xrh[MAXN * HID];  // target-side transform (fp16)
__device__ float  g_out [MAXN * HID];       // layer output (valid at T1 nodes)
__device__ int    g_degc[MAXN];             // degree per T1 index (zero at entry)
__device__ int    g_mark1[MAXN];            // T1 index+1 (valid only where bm1 set)
__device__ uint   g_bm1 [NBM];              // T1 bitmask (zeroed by fin)
__device__ uint   g_bm2 [NBM];              // T2 bitmask (zeroed by fin)
__device__ int    g_rowptr[MAXN + 1];       // compact rowptr over T1 indices
__device__ int    g_cur [MAXN];
__device__ int    g_bsum[128];
__device__ int    g_csr_src[MAXETP];        // src node per compact slot
__device__ int    g_list1[MAXN];            // compacted T1 node list
__device__ int    g_list2[MAXN];            // compacted T2 node list
__device__ int2   g_pair_es[MAXET];         // (eid, src) of accepted edges
__device__ int2   g_pair_md[MAXET];         // (T1 idx, dst) of accepted edges
__device__ int    g_n1, g_n2, g_np;         // zero at entry (fin restores)
__device__ __align__(16) __half g_eap[(size_t)MAXETP * FE];  // permuted fp16 edge attrs

// ---------------- small helpers ---------------------------------------------
__device__ __forceinline__ void mma_f16(float acc[4], uint a0, uint a1, uint a2, uint a3,
                                        uint b0, uint b1) {
    asm volatile(
        "mma.sync.aligned.m16n8k16.row.col.f32.f16.f16.f32 "
        "{%0,%1,%2,%3}, {%4,%5,%6,%7}, {%8,%9}, {%0,%1,%2,%3};"
        : "+f"(acc[0]), "+f"(acc[1]), "+f"(acc[2]), "+f"(acc[3])
        : "r"(a0), "r"(a1), "r"(a2), "r"(a3), "r"(b0), "r"(b1));
}
__device__ __forceinline__ float2 h2f2(uint v) {
    __half2 h = *reinterpret_cast<__half2*>(&v);
    return __half22float2(h);
}
__device__ __forceinline__ uint f2h2(float x, float y) {
    __half2 h = __floats2half2_rn(x, y);
    return *reinterpret_cast<uint*>(&h);
}
__device__ __forceinline__ bool bm_test(const uint* bm, int i) {
    return (bm[i >> 5] >> (i & 31)) & 1u;
}

// ================= active-set construction ===================================
__global__ void mark2_kernel(const int* __restrict__ nidx, int M) {
    int m = blockIdx.x * blockDim.x + threadIdx.x;
    if (m >= M) return;
    int d = nidx[m];
    uint bit = 1u << (d & 31);
    if (!(atomicOr(&g_bm2[d >> 5], bit) & bit)) {
        int p = atomicAdd(&g_n2, 1); g_list2[p] = d;
    }
    if (!(atomicOr(&g_bm1[d >> 5], bit) & bit)) {
        int p = atomicAdd(&g_n1, 1); g_list1[p] = d; g_mark1[d] = p + 1;
    }
}

// T1 += sources of edges whose dst is in T2 (bit probe, L1-resident bitmask)
__global__ void markS_kernel(const int* __restrict__ ei, int E) {
    int i = blockIdx.x * blockDim.x + threadIdx.x;
    if (i >= E) return;
    int d = ei[E + i];
    if (bm_test(g_bm2, d)) {
        int s = ei[i];
        uint bit = 1u << (s & 31);
        if (!(atomicOr(&g_bm1[s >> 5], bit) & bit)) {
            int p = atomicAdd(&g_n1, 1); g_list1[p] = s; g_mark1[s] = p + 1;
        }
    }
}

// ================= compact CSR build (T1 segments only) =======================
// Single E-scan: bit probe, warp-aggregated append, degree count.
__global__ void collect_kernel(const int* __restrict__ ei, int E) {
    int i = blockIdx.x * blockDim.x + threadIdx.x;
    bool acc = false;
    int d = 0, m = 0;
    if (i < E) {
        d = ei[E + i];
        acc = bm_test(g_bm1, d);
    }
    uint mask = __ballot_sync(0xffffffffu, acc);
    if (!mask) return;
    int lane = threadIdx.x & 31;
    int base;
    if (lane == __ffs(mask) - 1) base = atomicAdd(&g_np, __popc(mask));
    base = __shfl_sync(0xffffffffu, base, __ffs(mask) - 1);
    if (acc) {
        int j = base + __popc(mask & ((1u << lane) - 1u));
        m = g_mark1[d] - 1;
        g_pair_es[j] = make_int2(i, ei[i]);
        g_pair_md[j] = make_int2(m, d);
        atomicAdd(&g_degc[m], 1);
    }
}

// grid scan stage A over T1-index space: exclusive scan of (deg+1)
__global__ __launch_bounds__(1024) void scanA_kernel() {
    __shared__ int wsum[32];
    const int n1 = g_n1;
    const int i = blockIdx.x * 1024 + threadIdx.x;
    const int lane = threadIdx.x & 31, wid = threadIdx.x >> 5;
    int v = (i < n1) ? (g_degc[i] + 1) : 0;
    int s = v;
    #pragma unroll
    for (int off = 1; off < 32; off <<= 1) {
        int t = __shfl_up_sync(0xffffffffu, s, off);
        if (lane >= off) s += t;
    }
    if (lane == 31) wsum[wid] = s;
    __syncthreads();
    if (wid == 0) {
        int ws = wsum[lane];
        #pragma unroll
        for (int off = 1; off < 32; off <<= 1) {
            int t = __shfl_up_sync(0xffffffffu, ws, off);
            if (lane >= off) ws += t;
        }
        wsum[lane] = ws;
    }
    __syncthreads();
    int excl = s - v + (wid ? wsum[wid - 1] : 0);
    if (i < n1) g_rowptr[i] = excl;
    if (threadIdx.x == 1023) g_bsum[blockIdx.x] = excl + v;
}

__global__ void scanB_kernel(int nb) {
    __shared__ int sh[128];
    const int t = threadIdx.x;
    int v = (t < nb) ? g_bsum[t] : 0;
    sh[t] = v;
    __syncthreads();
    for (int off = 1; off < 128; off <<= 1) {
        int x = (t >= off) ? sh[t - off] : 0;
        __syncthreads();
        sh[t] += x;
        __syncthreads();
    }
    g_bsum[t] = sh[t] - v;
    if (t == 127) g_rowptr[g_n1] = sh[127];
}

__global__ __launch_bounds__(1024) void scanC_kernel() {
    const int n1 = g_n1;
    int i = blockIdx.x * 1024 + threadIdx.x;
    if (i < n1) {
        int rp = g_rowptr[i] + g_bsum[blockIdx.x];
        g_rowptr[i] = rp;
        g_cur[i]    = rp;
    }
}

// place accepted edges into compact slots + permute/convert edge attrs
__global__ void place_kernel(const float* __restrict__ ea) {
    const int np = g_np;
    const int stride = gridDim.x * blockDim.x;
    for (int j = blockIdx.x * blockDim.x + threadIdx.x; j < np; j += stride) {
        int2 es = g_pair_es[j];
        int2 md = g_pair_md[j];
        int pos = atomicAdd(&g_cur[md.x], 1);
        g_csr_src[pos] = es.y;
        const float4* r4 = reinterpret_cast<const float4*>(ea) + (size_t)es.x * 8;
        __half2* dst = reinterpret_cast<__half2*>(g_eap + (size_t)pos * FE);
        #pragma unroll
        for (int q = 0; q < 8; ++q) {
            float4 v = r4[q];
            dst[2 * q]     = __floats2half2_rn(v.x, v.y);
            dst[2 * q + 1] = __floats2half2_rn(v.z, v.w);
        }
    }
}

// self-loop mean per T1 segment (fills last slot of each segment)
__global__ void prep_kernel() {
    const int lane = threadIdx.x & 31;
    const int gws = gridDim.x * 8;
    const int n1 = g_n1;
    for (int widx = blockIdx.x * 8 + (threadIdx.x >> 5); widx < n1; widx += gws) {
        const int d = g_list1[widx];
        const int rp0 = g_rowptr[widx], rp1 = g_rowptr[widx + 1];
        const int last = rp1 - 1;            // self-loop slot
        float s = 0.f;
        int e = rp0;
        for (; e + 4 <= last; e += 4) {
            float a0 = __half2float(g_eap[(size_t)(e + 0) * FE + lane]);
            float a1 = __half2float(g_eap[(size_t)(e + 1) * FE + lane]);
            float a2 = __half2float(g_eap[(size_t)(e + 2) * FE + lane]);
            float a3 = __half2float(g_eap[(size_t)(e + 3) * FE + lane]);
            s += (a0 + a1) + (a2 + a3);
        }
        for (; e < last; ++e) s += __half2float(g_eap[(size_t)e * FE + lane]);
        float mean = s / (float)max(last - rp0, 1);
        g_eap[(size_t)last * FE + lane] = __float2half_rn(mean);
        if (lane == 0) g_csr_src[last] = d;
    }
}

// ---------------- single-output node linear via fp16 tensor MMA --------------
template<int IN, int SET, bool HPREV>
__global__ __launch_bounds__(256) void lin_f16_kernel(
        const float* __restrict__ inp, const float* __restrict__ W,
        const float* __restrict__ bias, const float* __restrict__ prevBias,
        int N, int right) {
    const int nlim = (SET == 0) ? N : (SET == 1 ? g_n1 : g_n2);
    const int nb = blockIdx.x * 128;
    if (nb >= nlim) return;

    constexpr int KC = 16;                    // k per iteration (one k16 MMA step)
    __shared__ uint Xs[128][9];               // 8 k-pair words + pad
    __shared__ uint Ws[8][68];                // k-pair word x 64 cols + pad

    const int t = threadIdx.x;
    const int lane = t & 31;
    const int mt = t >> 5;                    // warp = m-tile 0..7
    const int g = lane >> 2, c = lane & 3;

    float acc[8][4];
    #pragma unroll
    for (int nt = 0; nt < 8; ++nt) {
        acc[nt][0] = acc[nt][1] = acc[nt][2] = acc[nt][3] = 0.f;
    }

    for (int kc = 0; kc < IN; kc += KC) {
        __syncthreads();
        for (int idx = t; idx < 128 * 8; idx += 256) {
            int row = idx >> 3, kw = idx & 7;
            int m = nb + row;
            float v0 = 0.f, v1 = 0.f;
            if (m < nlim) {
                int node = (SET == 0) ? m : (SET == 1 ? g_list1[m] : g_list2[m]);
                int j = kc + 2 * kw;
                if (HPREV) {
                    float2 hv = *reinterpret_cast<const float2*>(g_out + (size_t)node * HID + j);
                    v0 = fmaxf(hv.x + prevBias[j], 0.f);
                    v1 = fmaxf(hv.y + prevBias[j + 1], 0.f);
                } else {
                    float2 xv = *reinterpret_cast<const float2*>(inp + (size_t)node * IN + j);
                    v0 = xv.x; v1 = xv.y;
                }
            }
            Xs[row][kw] = f2h2(v0, v1);
        }
        for (int idx = t; idx < 8 * 64; idx += 256) {
            int kw = idx >> 6, col = idx & 63;
            int k = kc + 2 * kw;
            Ws[kw][col] = f2h2(W[k * HID + col], W[(k + 1) * HID + col]);
        }
        __syncthreads();
        uint a0 = Xs[mt * 16 + g    ][c];
        uint a1 = Xs[mt * 16 + g + 8][c];
        uint a2 = Xs[mt * 16 + g    ][c + 4];
        uint a3 = Xs[mt * 16 + g + 8][c + 4];
        #pragma unroll
        for (int nt = 0; nt < 8; ++nt) {
            int col = nt * 8 + g;
            mma_f16(acc[nt], a0, a1, a2, a3, Ws[c][col], Ws[c + 4][col]);
        }
    }

    uint* dsth = reinterpret_cast<uint*>(right ? g_xrh : g_xlh);
    const int m0 = nb + mt * 16 + g;
    const int m1 = m0 + 8;
    const int node0 = (m0 < nlim) ? ((SET == 0) ? m0 : (SET == 1 ? g_list1[m0] : g_list2[m0])) : -1;
    const int node1 = (m1 < nlim) ? ((SET == 0) ? m1 : (SET == 1 ? g_list1[m1] : g_list2[m1])) : -1;
    #pragma unroll
    for (int nt = 0; nt < 8; ++nt) {
        int colL = nt * 8 + 2 * c;
        float bx = bias[colL], by = bias[colL + 1];
        if (node0 >= 0)
            dsth[(size_t)node0 * 32 + nt * 4 + c] = f2h2(acc[nt][0] + bx, acc[nt][1] + by);
        if (node1 >= 0)
            dsth[(size_t)node1 * 32 + nt * 4 + c] = f2h2(acc[nt][2] + bx, acc[nt][3] + by);
    }
}

// ---------------- fused edge pass: warp-per-segment GATv2 --------------------
__global__ __launch_bounds__(256) void edge_fused_kernel(
        const float* __restrict__ We, const float* __restrict__ att, int layer) {
    const int n = (layer == 1) ? g_n1 : g_n2;
    const int t = threadIdx.x;
    const int lane = t & 31;
    const int g = lane >> 2;                 // row group 0..7
    const int c = lane & 3;                  // col-in-group 0..3
    const int gws = gridDim.x * 8;

    // preload B fragments (We as fp16) and att pairs into registers
    uint breg[8][2][2];
    float2 areg[8];
    #pragma unroll
    for (int nt = 0; nt < 8; ++nt) {
        const int nn = nt * 8 + g;
        #pragma unroll
        for (int ks = 0; ks < 2; ++ks) {
            int k0 = ks * 16 + 2 * c;
            breg[nt][ks][0] = f2h2(We[k0 * HID + nn],       We[(k0 + 1) * HID + nn]);
            breg[nt][ks][1] = f2h2(We[(k0 + 8) * HID + nn], We[(k0 + 9) * HID + nn]);
        }
        areg[nt] = reinterpret_cast<const float2*>(att)[nt * 4 + c];
    }

    const uint* xlh = reinterpret_cast<const uint*>(g_xlh);
    const uint* xrh = reinterpret_cast<const uint*>(g_xrh);

    for (int widx = blockIdx.x * 8 + (t >> 5); widx < n; widx += gws) {
        int d, m;
        if (layer == 1) { d = g_list1[widx]; m = widx; }
        else            { d = g_list2[widx]; m = g_mark1[d] - 1; }
        const int rp0 = g_rowptr[m], rp1 = g_rowptr[m + 1];

        // xr[d] loaded once per segment
        float2 xr[8];
        #pragma unroll
        for (int nt = 0; nt < 8; ++nt)
            xr[nt] = h2f2(xrh[(size_t)d * 32 + nt * 4 + c]);

        float den = 0.f;
        float2 o[8];
        #pragma unroll
        for (int nt = 0; nt < 8; ++nt) o[nt] = make_float2(0.f, 0.f);

        for (int base = rp0; base < rp1; base += 16) {
            const int rowA = base + g;
            const int rowB = rowA + 8;
            const bool vA = rowA < rp1, vB = rowB < rp1;
            const int slotA = vA ? rowA : MAXET;   // pad slot: zeros
            const int slotB = vB ? rowB : MAXET;
            const int sA = g_csr_src[slotA], sB = g_csr_src[slotB];
            const uint* pA = reinterpret_cast<const uint*>(g_eap + (size_t)slotA * FE);
            const uint* pB = reinterpret_cast<const uint*>(g_eap + (size_t)slotB * FE);

            uint afr[2][4];
            #pragma unroll
            for (int ks = 0; ks < 2; ++ks) {
                afr[ks][0] = pA[ks * 8 + c];
                afr[ks][1] = pB[ks * 8 + c];
                afr[ks][2] = pA[ks * 8 + c + 4];
                afr[ks][3] = pB[ks * 8 + c + 4];
            }

            float2 xlA[8], xlB[8];
            float partA = 0.f, partB = 0.f;
            #pragma unroll
            for (int nt = 0; nt < 8; ++nt) {
                float acc[4] = {0.f, 0.f, 0.f, 0.f};
                mma_f16(acc, afr[0][0], afr[0][1], afr[0][2], afr[0][3],
                        breg[nt][0][0], breg[nt][0][1]);
                mma_f16(acc, afr[1][0], afr[1][1], afr[1][2], afr[1][3],
                        breg[nt][1][0], breg[nt][1][1]);
                xlA[nt] = h2f2(xlh[(size_t)sA * 32 + nt * 4 + c]);
                xlB[nt] = h2f2(xlh[(size_t)sB * 32 + nt * 4 + c]);
                float u0 = acc[0] + xlA[nt].x + xr[nt].x;
                float u1 = acc[1] + xlA[nt].y + xr[nt].y;
                float u2 = acc[2] + xlB[nt].x + xr[nt].x;
                float u3 = acc[3] + xlB[nt].y + xr[nt].y;
                u0 = fmaxf(u0, 0.f) + 0.2f * fminf(u0, 0.f);
                u1 = fmaxf(u1, 0.f) + 0.2f * fminf(u1, 0.f);
                u2 = fmaxf(u2, 0.f) + 0.2f * fminf(u2, 0.f);
                u3 = fmaxf(u3, 0.f) + 0.2f * fminf(u3, 0.f);
                partA = fmaf(u0, areg[nt].x, fmaf(u1, areg[nt].y, partA));
                partB = fmaf(u2, areg[nt].x, fmaf(u3, areg[nt].y, partB));
            }
            partA += __shfl_xor_sync(0xffffffffu, partA, 1);
            partA += __shfl_xor_sync(0xffffffffu, partA, 2);
            partB += __shfl_xor_sync(0xffffffffu, partB, 1);
            partB += __shfl_xor_sync(0xffffffffu, partB, 2);
            const float eA = vA ? __expf(partA) : 0.f;
            const float eB = vB ? __expf(partB) : 0.f;
            den += eA + eB;
            #pragma unroll
            for (int nt = 0; nt < 8; ++nt) {
                o[nt].x = fmaf(eA, xlA[nt].x, fmaf(eB, xlB[nt].x, o[nt].x));
                o[nt].y = fmaf(eA, xlA[nt].y, fmaf(eB, xlB[nt].y, o[nt].y));
            }
        }

        // reduce across the 8 row-groups (lane = g*4 + c)
        #pragma unroll
        for (int off = 4; off <= 16; off <<= 1) {
            den += __shfl_xor_sync(0xffffffffu, den, off);
            #pragma unroll
            for (int nt = 0; nt < 8; ++nt) {
                o[nt].x += __shfl_xor_sync(0xffffffffu, o[nt].x, off);
                o[nt].y += __shfl_xor_sync(0xffffffffu, o[nt].y, off);
            }
        }
        const float inv = 1.f / den;
        if (g == 0) {
            float2* out2 = reinterpret_cast<float2*>(g_out);
            #pragma unroll
            for (int nt = 0; nt < 8; ++nt)
                out2[(size_t)d * 32 + nt * 4 + c] = make_float2(o[nt].x * inv, o[nt].y * inv);
        }
    }
}

// ---------------- final MLP at node_idx + restore zero-invariants ------------
__global__ void fin_kernel(const int* __restrict__ idx, const float* __restrict__ bias2,
                           const float* __restrict__ y,
                           const float* __restrict__ W0, const float* __restrict__ b0,
                           const float* __restrict__ W1, const float* __restrict__ b1,
                           const float* __restrict__ W2, const float* __restrict__ b2,
                           float* __restrict__ dout, int M, int rf, int N) {
    // restore zero-invariants for the next launch (graph replay safe)
    int tid = blockIdx.x * blockDim.x + threadIdx.x;
    for (int z = tid; z < N; z += gridDim.x * blockDim.x) g_degc[z] = 0;
    for (int z = tid; z < NBM; z += gridDim.x * blockDim.x) { g_bm1[z] = 0u; g_bm2[z] = 0u; }
    if (tid == 0) { g_n1 = 0; g_n2 = 0; g_np = 0; }

    __shared__ float sh[4][64];
    __shared__ float sz[4][32];
    const int w = threadIdx.x >> 5, lane = threadIdx.x & 31;
    const int m = blockIdx.x * 4 + w;
    if (m >= M) return;
    const int v = idx[m];

    float h0 = fmaxf(g_out[(size_t)v * HID + lane]      + bias2[lane],      0.f);
    float h1 = fmaxf(g_out[(size_t)v * HID + 32 + lane] + bias2[32 + lane], 0.f);
    sh[w][lane] = h0; sh[w][32 + lane] = h1;
    __syncwarp();

    int k = v / rf;
    float y0 = y[2 * k], y1 = y[2 * k + 1];
    float q0 = fmaxf(y0 * W0[0] + y1 * W0[2] + b0[0], 0.f);
    float q1 = fmaxf(y0 * W0[1] + y1 * W0[3] + b0[1], 0.f);

    float z = b1[lane];
    #pragma unroll
    for (int j = 0; j < 64; ++j) z += sh[w][j] * W1[j * 32 + lane];
    z += q0 * W1[64 * 32 + lane] + q1 * W1[65 * 32 + lane];
    z = fmaxf(z, 0.f);
    sz[w][lane] = z;
    __syncwarp();

    float o = b2[lane];
    #pragma unroll
    for (int j = 0; j < 32; ++j) o += sz[w][j] * W2[j * 32 + lane];
    dout[m * 32 + lane] = o;
}

// ---------------- launch ------------------------------------------------------
extern "C" void kernel_launch(void* const* d_in, const int* in_sizes, int n_in,
                              void* d_out, int out_size) {
    const float* x    = (const float*)d_in[0];
    const float* ea   = (const float*)d_in[1];
    const float* y    = (const float*)d_in[2];
    const float* Wl1  = (const float*)d_in[3];
    const float* bl1  = (const float*)d_in[4];
    const float* Wr1  = (const float*)d_in[5];
    const float* br1  = (const float*)d_in[6];
    const float* We1  = (const float*)d_in[7];
    const float* att1 = (const float*)d_in[8];
    const float* bias1= (const float*)d_in[9];
    const float* Wl2  = (const float*)d_in[10];
    const float* bl2  = (const float*)d_in[11];
    const float* Wr2  = (const float*)d_in[12];
    const float* br2  = (const float*)d_in[13];
    const float* We2  = (const float*)d_in[14];
    const float* att2 = (const float*)d_in[15];
    const float* bias2= (const float*)d_in[16];
    const float* W0   = (const float*)d_in[17];
    const float* b0   = (const float*)d_in[18];
    const float* W1   = (const float*)d_in[19];
    const float* b1   = (const float*)d_in[20];
    const float* W2   = (const float*)d_in[21];
    const float* b2   = (const float*)d_in[22];
    const int*   ei   = (const int*)  d_in[23];
    const int*   nidx = (const int*)  d_in[24];

    const int N    = in_sizes[0] / FN;
    const int E    = in_sizes[23] / 2;
    const int M    = in_sizes[24];
    const int NG   = in_sizes[2] / 2;
    const int rf   = N / NG;

    const int EBLK = (E + 255) / 256;
    const int NB1K = (N + 1023) / 1024;
    const int LINB = (N + 127) / 128;

    // ---- active sets (bitmask probes) ----
    mark2_kernel   <<<(M + 255) / 256, 256>>>(nidx, M);
    markS_kernel   <<<EBLK, 256>>>(ei, E);

    // ---- compact CSR over T1 (one E-scan + 3-stage grid scan) ----
    collect_kernel <<<EBLK, 256>>>(ei, E);
    scanA_kernel   <<<NB1K, 1024>>>();
    scanB_kernel   <<<1, 128>>>(NB1K);
    scanC_kernel   <<<NB1K, 1024>>>();
    place_kernel   <<<1024, 256>>>(ea);
    prep_kernel    <<<512, 256>>>();

    // ---- layer 1: xl over all N, xr over T1; fused edge pass over T1 ----
    lin_f16_kernel<FN, 0, false><<<LINB, 256>>>(x, Wl1, bl1, nullptr, N, 0);
    lin_f16_kernel<FN, 1, false><<<LINB, 256>>>(x, Wr1, br1, nullptr, N, 1);
    edge_fused_kernel<<<1024, 256>>>(We1, att1, 1);

    // ---- layer 2: xl over T1, xr over T2; fused edge pass over T2 ----
    lin_f16_kernel<HID, 1, true><<<LINB, 256>>>(x, Wl2, bl2, bias1, N, 0);
    lin_f16_kernel<HID, 2, true><<<LINB, 256>>>(x, Wr2, br2, bias1, N, 1);
    edge_fused_kernel<<<128, 256>>>(We2, att2, 2);

    // ---- final MLP at node_idx (also restores zero-invariants) ----
    fin_kernel<<<512, 128>>>(nidx, bias2, y, W0, b0, W1, b1, W2, b2,
                             (float*)d_out, M, rf, N);
}

// round 16
// speedup vs baseline: 1.1451x; 1.0902x over previous
#include <cuda_runtime.h>
#include <cuda_fp16.h>
#include <cstddef>

typedef unsigned long long ull;
typedef unsigned int uint;

// ---------------- problem constants (shapes fixed by the dataset) -----------
#define MAXN 100000
#define MAXE 1600000
#define MAXET (MAXE + MAXN)
#define MAXETP (MAXET + 16)   // padded: slot MAXET is a never-written zero row
#define NBM  ((MAXN + 31) / 32)
#define NSCB 128              // scan lookback state slots (>= grid blocks)
#define FN   128     // node feature dim (layer1 input)
#define FE   32      // edge feature dim
#define HID  64

// ---------------- device scratch (static: no allocation allowed) ------------
__device__ __align__(16) __half g_xlh[MAXN * HID];  // source-side transform (fp16)
__device__ __align__(16) __half g_xrh[MAXN * HID];  // target-side transform (fp16)
__device__ float  g_out [MAXN * HID];       // layer output (valid at T1 nodes)
__device__ int    g_degc[MAXN];             // degree per T1 index (zero at entry)
__device__ int    g_mark1[MAXN];            // T1 index+1 (valid only where bm1 set)
__device__ uint   g_bm1 [NBM];              // T1 bitmask (zeroed by fin)
__device__ uint   g_bm2 [NBM];              // T2 bitmask (zeroed by fin)
__device__ int    g_rowptr[MAXN + 1];       // compact rowptr over T1 indices
__device__ int    g_cur [MAXN];
__device__ ull    g_blk_state[NSCB];        // lookback: (flag<<32)|value, zero at entry
__device__ int    g_csr_src[MAXETP];        // src node per compact slot
__device__ int    g_list1[MAXN];            // compacted T1 node list
__device__ int    g_list2[MAXN];            // compacted T2 node list
__device__ int2   g_pair_es[MAXET];         // (eid, src) of accepted edges
__device__ int2   g_pair_md[MAXET];         // (T1 idx, dst) of accepted edges
__device__ int    g_n1, g_n2, g_np;         // zero at entry (fin restores)
__device__ __align__(16) __half g_eap[(size_t)MAXETP * FE];  // permuted fp16 edge attrs

// ---------------- small helpers ---------------------------------------------
__device__ __forceinline__ void mma_f16(float acc[4], uint a0, uint a1, uint a2, uint a3,
                                        uint b0, uint b1) {
    asm volatile(
        "mma.sync.aligned.m16n8k16.row.col.f32.f16.f16.f32 "
        "{%0,%1,%2,%3}, {%4,%5,%6,%7}, {%8,%9}, {%0,%1,%2,%3};"
        : "+f"(acc[0]), "+f"(acc[1]), "+f"(acc[2]), "+f"(acc[3])
        : "r"(a0), "r"(a1), "r"(a2), "r"(a3), "r"(b0), "r"(b1));
}
__device__ __forceinline__ float2 h2f2(uint v) {
    __half2 h = *reinterpret_cast<__half2*>(&v);
    return __half22float2(h);
}
__device__ __forceinline__ uint f2h2(float x, float y) {
    __half2 h = __floats2half2_rn(x, y);
    return *reinterpret_cast<uint*>(&h);
}
__device__ __forceinline__ bool bm_test(const uint* bm, int i) {
    return (bm[i >> 5] >> (i & 31)) & 1u;
}

// ================= active-set construction ===================================
__global__ void mark2_kernel(const int* __restrict__ nidx, int M) {
    int m = blockIdx.x * blockDim.x + threadIdx.x;
    if (m >= M) return;
    int d = nidx[m];
    uint bit = 1u << (d & 31);
    if (!(atomicOr(&g_bm2[d >> 5], bit) & bit)) {
        int p = atomicAdd(&g_n2, 1); g_list2[p] = d;
    }
    if (!(atomicOr(&g_bm1[d >> 5], bit) & bit)) {
        int p = atomicAdd(&g_n1, 1); g_list1[p] = d; g_mark1[d] = p + 1;
    }
}

// T1 += sources of edges whose dst is in T2 (bit probe, L1-resident bitmask)
__global__ void markS_kernel(const int* __restrict__ ei, int E) {
    int i = blockIdx.x * blockDim.x + threadIdx.x;
    if (i >= E) return;
    int d = ei[E + i];
    if (bm_test(g_bm2, d)) {
        int s = ei[i];
        uint bit = 1u << (s & 31);
        if (!(atomicOr(&g_bm1[s >> 5], bit) & bit)) {
            int p = atomicAdd(&g_n1, 1); g_list1[p] = s; g_mark1[s] = p + 1;
        }
    }
}

// ================= compact CSR build (T1 segments only) =======================
// Single E-scan: bit probe, warp-aggregated append, degree count.
__global__ void collect_kernel(const int* __restrict__ ei, int E) {
    int i = blockIdx.x * blockDim.x + threadIdx.x;
    bool acc = false;
    int d = 0, m = 0;
    if (i < E) {
        d = ei[E + i];
        acc = bm_test(g_bm1, d);
    }
    uint mask = __ballot_sync(0xffffffffu, acc);
    if (!mask) return;
    int lane = threadIdx.x & 31;
    int base;
    if (lane == __ffs(mask) - 1) base = atomicAdd(&g_np, __popc(mask));
    base = __shfl_sync(0xffffffffu, base, __ffs(mask) - 1);
    if (acc) {
        int j = base + __popc(mask & ((1u << lane) - 1u));
        m = g_mark1[d] - 1;
        g_pair_es[j] = make_int2(i, ei[i]);
        g_pair_md[j] = make_int2(m, d);
        atomicAdd(&g_degc[m], 1);
    }
}

// single-pass decoupled-lookback scan over T1 indices: rowptr/cur from (deg+1)
__global__ __launch_bounds__(1024) void scan_lb_kernel() {
    __shared__ int wsum[32];
    __shared__ int s_excl;
    const int n1 = g_n1;
    const int bid = blockIdx.x;
    const int i = bid * 1024 + threadIdx.x;
    const int lane = threadIdx.x & 31, wid = threadIdx.x >> 5;

    int v = (i < n1) ? (g_degc[i] + 1) : 0;
    int s = v;
    #pragma unroll
    for (int off = 1; off < 32; off <<= 1) {
        int t = __shfl_up_sync(0xffffffffu, s, off);
        if (lane >= off) s += t;
    }
    if (lane == 31) wsum[wid] = s;
    __syncthreads();
    if (wid == 0) {
        int ws = wsum[lane];
        #pragma unroll
        for (int off = 1; off < 32; off <<= 1) {
            int t = __shfl_up_sync(0xffffffffu, ws, off);
            if (lane >= off) ws += t;
        }
        wsum[lane] = ws;
    }
    __syncthreads();
    const int excl_in_blk = s - v + (wid ? wsum[wid - 1] : 0);
    const int block_total = wsum[31];

    if (threadIdx.x == 0) {
        int excl = 0;
        if (bid == 0) {
            atomicExch(&g_blk_state[0], ((ull)2 << 32) | (uint)block_total);
        } else {
            atomicExch(&g_blk_state[bid], ((ull)1 << 32) | (uint)block_total);
            int j = bid - 1;
            while (true) {
                ull st;
                do { st = atomicOr(&g_blk_state[j], 0ull); } while ((st >> 32) == 0);
                excl += (int)(st & 0xffffffffu);
                if ((st >> 32) == 2) break;
                --j;
            }
            atomicExch(&g_blk_state[bid], ((ull)2 << 32) | (uint)(excl + block_total));
        }
        s_excl = excl;
        if (bid == gridDim.x - 1) g_rowptr[n1] = excl + block_total;
    }
    __syncthreads();
    if (i < n1) {
        int rp = s_excl + excl_in_blk;
        g_rowptr[i] = rp;
        g_cur[i]    = rp;
    }
}

// place accepted edges into compact slots + permute/convert edge attrs
__global__ void place_kernel(const float* __restrict__ ea) {
    const int np = g_np;
    const int stride = gridDim.x * blockDim.x;
    for (int j = blockIdx.x * blockDim.x + threadIdx.x; j < np; j += stride) {
        int2 es = g_pair_es[j];
        int2 md = g_pair_md[j];
        int pos = atomicAdd(&g_cur[md.x], 1);
        g_csr_src[pos] = es.y;
        const float4* r4 = reinterpret_cast<const float4*>(ea) + (size_t)es.x * 8;
        __half2* dst = reinterpret_cast<__half2*>(g_eap + (size_t)pos * FE);
        #pragma unroll
        for (int q = 0; q < 8; ++q) {
            float4 v = r4[q];
            dst[2 * q]     = __floats2half2_rn(v.x, v.y);
            dst[2 * q + 1] = __floats2half2_rn(v.z, v.w);
        }
    }
}

// self-loop mean per T1 segment (fills last slot of each segment)
__global__ void prep_kernel() {
    const int lane = threadIdx.x & 31;
    const int gws = gridDim.x * 8;
    const int n1 = g_n1;
    for (int widx = blockIdx.x * 8 + (threadIdx.x >> 5); widx < n1; widx += gws) {
        const int d = g_list1[widx];
        const int rp0 = g_rowptr[widx], rp1 = g_rowptr[widx + 1];
        const int last = rp1 - 1;            // self-loop slot
        float s = 0.f;
        int e = rp0;
        for (; e + 4 <= last; e += 4) {
            float a0 = __half2float(g_eap[(size_t)(e + 0) * FE + lane]);
            float a1 = __half2float(g_eap[(size_t)(e + 1) * FE + lane]);
            float a2 = __half2float(g_eap[(size_t)(e + 2) * FE + lane]);
            float a3 = __half2float(g_eap[(size_t)(e + 3) * FE + lane]);
            s += (a0 + a1) + (a2 + a3);
        }
        for (; e < last; ++e) s += __half2float(g_eap[(size_t)e * FE + lane]);
        float mean = s / (float)max(last - rp0, 1);
        g_eap[(size_t)last * FE + lane] = __float2half_rn(mean);
        if (lane == 0) g_csr_src[last] = d;
    }
}

// ---------------- single-output node linear body (fp16 tensor MMA) -----------
// SET: 0 = full N, 1 = g_list1, 2 = g_list2. HPREV: read g_out+bias1+relu.
template<int IN, int SET, bool HPREV>
__device__ __forceinline__ void lin_body(
        const float* __restrict__ inp, const float* __restrict__ W,
        const float* __restrict__ bias, const float* __restrict__ prevBias,
        int N, int right, int blk) {
    const int nlim = (SET == 0) ? N : (SET == 1 ? g_n1 : g_n2);
    const int nb = blk * 128;
    if (nb >= nlim) return;

    constexpr int KC = 16;
    __shared__ uint Xs[128][9];
    __shared__ uint Ws[8][68];

    const int t = threadIdx.x;
    const int lane = t & 31;
    const int mt = t >> 5;
    const int g = lane >> 2, c = lane & 3;

    float acc[8][4];
    #pragma unroll
    for (int nt = 0; nt < 8; ++nt) {
        acc[nt][0] = acc[nt][1] = acc[nt][2] = acc[nt][3] = 0.f;
    }

    for (int kc = 0; kc < IN; kc += KC) {
        __syncthreads();
        for (int idx = t; idx < 128 * 8; idx += 256) {
            int row = idx >> 3, kw = idx & 7;
            int m = nb + row;
            float v0 = 0.f, v1 = 0.f;
            if (m < nlim) {
                int node = (SET == 0) ? m : (SET == 1 ? g_list1[m] : g_list2[m]);
                int j = kc + 2 * kw;
                if (HPREV) {
                    float2 hv = *reinterpret_cast<const float2*>(g_out + (size_t)node * HID + j);
                    v0 = fmaxf(hv.x + prevBias[j], 0.f);
                    v1 = fmaxf(hv.y + prevBias[j + 1], 0.f);
                } else {
                    float2 xv = *reinterpret_cast<const float2*>(inp + (size_t)node * IN + j);
                    v0 = xv.x; v1 = xv.y;
                }
            }
            Xs[row][kw] = f2h2(v0, v1);
        }
        for (int idx = t; idx < 8 * 64; idx += 256) {
            int kw = idx >> 6, col = idx & 63;
            int k = kc + 2 * kw;
            Ws[kw][col] = f2h2(W[k * HID + col], W[(k + 1) * HID + col]);
        }
        __syncthreads();
        uint a0 = Xs[mt * 16 + g    ][c];
        uint a1 = Xs[mt * 16 + g + 8][c];
        uint a2 = Xs[mt * 16 + g    ][c + 4];
        uint a3 = Xs[mt * 16 + g + 8][c + 4];
        #pragma unroll
        for (int nt = 0; nt < 8; ++nt) {
            int col = nt * 8 + g;
            mma_f16(acc[nt], a0, a1, a2, a3, Ws[c][col], Ws[c + 4][col]);
        }
    }

    uint* dsth = reinterpret_cast<uint*>(right ? g_xrh : g_xlh);
    const int m0 = nb + mt * 16 + g;
    const int m1 = m0 + 8;
    const int node0 = (m0 < nlim) ? ((SET == 0) ? m0 : (SET == 1 ? g_list1[m0] : g_list2[m0])) : -1;
    const int node1 = (m1 < nlim) ? ((SET == 0) ? m1 : (SET == 1 ? g_list1[m1] : g_list2[m1])) : -1;
    #pragma unroll
    for (int nt = 0; nt < 8; ++nt) {
        int colL = nt * 8 + 2 * c;
        float bx = bias[colL], by = bias[colL + 1];
        if (node0 >= 0)
            dsth[(size_t)node0 * 32 + nt * 4 + c] = f2h2(acc[nt][0] + bx, acc[nt][1] + by);
        if (node1 >= 0)
            dsth[(size_t)node1 * 32 + nt * 4 + c] = f2h2(acc[nt][2] + bx, acc[nt][3] + by);
    }
}

// dual-output launch: first nblkA blocks compute xl (SETA), rest xr (SETB)
template<int IN, int SETA, int SETB, bool HPREV>
__global__ __launch_bounds__(256) void lin_dual_kernel(
        const float* __restrict__ inp,
        const float* __restrict__ WA, const float* __restrict__ bA,
        const float* __restrict__ WB, const float* __restrict__ bB,
        const float* __restrict__ prevBias, int N, int nblkA) {
    if ((int)blockIdx.x < nblkA)
        lin_body<IN, SETA, HPREV>(inp, WA, bA, prevBias, N, 0, blockIdx.x);
    else
        lin_body<IN, SETB, HPREV>(inp, WB, bB, prevBias, N, 1, blockIdx.x - nblkA);
}

// ---------------- fused edge pass: warp-per-segment GATv2 --------------------
__global__ __launch_bounds__(256) void edge_fused_kernel(
        const float* __restrict__ We, const float* __restrict__ att, int layer) {
    const int n = (layer == 1) ? g_n1 : g_n2;
    const int t = threadIdx.x;
    const int lane = t & 31;
    const int g = lane >> 2;                 // row group 0..7
    const int c = lane & 3;                  // col-in-group 0..3
    const int gws = gridDim.x * 8;

    // preload B fragments (We as fp16) and att pairs into registers
    uint breg[8][2][2];
    float2 areg[8];
    #pragma unroll
    for (int nt = 0; nt < 8; ++nt) {
        const int nn = nt * 8 + g;
        #pragma unroll
        for (int ks = 0; ks < 2; ++ks) {
            int k0 = ks * 16 + 2 * c;
            breg[nt][ks][0] = f2h2(We[k0 * HID + nn],       We[(k0 + 1) * HID + nn]);
            breg[nt][ks][1] = f2h2(We[(k0 + 8) * HID + nn], We[(k0 + 9) * HID + nn]);
        }
        areg[nt] = reinterpret_cast<const float2*>(att)[nt * 4 + c];
    }

    const uint* xlh = reinterpret_cast<const uint*>(g_xlh);
    const uint* xrh = reinterpret_cast<const uint*>(g_xrh);

    for (int widx = blockIdx.x * 8 + (t >> 5); widx < n; widx += gws) {
        int d, m;
        if (layer == 1) { d = g_list1[widx]; m = widx; }
        else            { d = g_list2[widx]; m = g_mark1[d] - 1; }
        const int rp0 = g_rowptr[m], rp1 = g_rowptr[m + 1];

        // xr[d] loaded once per segment
        float2 xr[8];
        #pragma unroll
        for (int nt = 0; nt < 8; ++nt)
            xr[nt] = h2f2(xrh[(size_t)d * 32 + nt * 4 + c]);

        float den = 0.f;
        float2 o[8];
        #pragma unroll
        for (int nt = 0; nt < 8; ++nt) o[nt] = make_float2(0.f, 0.f);

        for (int base = rp0; base < rp1; base += 16) {
            const int rowA = base + g;
            const int rowB = rowA + 8;
            const bool vA = rowA < rp1, vB = rowB < rp1;
            const int slotA = vA ? rowA : MAXET;   // pad slot: zeros
            const int slotB = vB ? rowB : MAXET;
            const int sA = g_csr_src[slotA], sB = g_csr_src[slotB];
            const uint* pA = reinterpret_cast<const uint*>(g_eap + (size_t)slotA * FE);
            const uint* pB = reinterpret_cast<const uint*>(g_eap + (size_t)slotB * FE);

            uint afr[2][4];
            #pragma unroll
            for (int ks = 0; ks < 2; ++ks) {
                afr[ks][0] = pA[ks * 8 + c];
                afr[ks][1] = pB[ks * 8 + c];
                afr[ks][2] = pA[ks * 8 + c + 4];
                afr[ks][3] = pB[ks * 8 + c + 4];
            }

            float2 xlA[8], xlB[8];
            float partA = 0.f, partB = 0.f;
            #pragma unroll
            for (int nt = 0; nt < 8; ++nt) {
                float acc[4] = {0.f, 0.f, 0.f, 0.f};
                mma_f16(acc, afr[0][0], afr[0][1], afr[0][2], afr[0][3],
                        breg[nt][0][0], breg[nt][0][1]);
                mma_f16(acc, afr[1][0], afr[1][1], afr[1][2], afr[1][3],
                        breg[nt][1][0], breg[nt][1][1]);
                xlA[nt] = h2f2(xlh[(size_t)sA * 32 + nt * 4 + c]);
                xlB[nt] = h2f2(xlh[(size_t)sB * 32 + nt * 4 + c]);
                float u0 = acc[0] + xlA[nt].x + xr[nt].x;
                float u1 = acc[1] + xlA[nt].y + xr[nt].y;
                float u2 = acc[2] + xlB[nt].x + xr[nt].x;
                float u3 = acc[3] + xlB[nt].y + xr[nt].y;
                u0 = fmaxf(u0, 0.f) + 0.2f * fminf(u0, 0.f);
                u1 = fmaxf(u1, 0.f) + 0.2f * fminf(u1, 0.f);
                u2 = fmaxf(u2, 0.f) + 0.2f * fminf(u2, 0.f);
                u3 = fmaxf(u3, 0.f) + 0.2f * fminf(u3, 0.f);
                partA = fmaf(u0, areg[nt].x, fmaf(u1, areg[nt].y, partA));
                partB = fmaf(u2, areg[nt].x, fmaf(u3, areg[nt].y, partB));
            }
            partA += __shfl_xor_sync(0xffffffffu, partA, 1);
            partA += __shfl_xor_sync(0xffffffffu, partA, 2);
            partB += __shfl_xor_sync(0xffffffffu, partB, 1);
            partB += __shfl_xor_sync(0xffffffffu, partB, 2);
            const float eA = vA ? __expf(partA) : 0.f;
            const float eB = vB ? __expf(partB) : 0.f;
            den += eA + eB;
            #pragma unroll
            for (int nt = 0; nt < 8; ++nt) {
                o[nt].x = fmaf(eA, xlA[nt].x, fmaf(eB, xlB[nt].x, o[nt].x));
                o[nt].y = fmaf(eA, xlA[nt].y, fmaf(eB, xlB[nt].y, o[nt].y));
            }
        }

        // reduce across the 8 row-groups (lane = g*4 + c)
        #pragma unroll
        for (int off = 4; off <= 16; off <<= 1) {
            den += __shfl_xor_sync(0xffffffffu, den, off);
            #pragma unroll
            for (int nt = 0; nt < 8; ++nt) {
                o[nt].x += __shfl_xor_sync(0xffffffffu, o[nt].x, off);
                o[nt].y += __shfl_xor_sync(0xffffffffu, o[nt].y, off);
            }
        }
        const float inv = 1.f / den;
        if (g == 0) {
            float2* out2 = reinterpret_cast<float2*>(g_out);
            #pragma unroll
            for (int nt = 0; nt < 8; ++nt)
                out2[(size_t)d * 32 + nt * 4 + c] = make_float2(o[nt].x * inv, o[nt].y * inv);
        }
    }
}

// ---------------- final MLP at node_idx + restore zero-invariants ------------
__global__ void fin_kernel(const int* __restrict__ idx, const float* __restrict__ bias2,
                           const float* __restrict__ y,
                           const float* __restrict__ W0, const float* __restrict__ b0,
                           const float* __restrict__ W1, const float* __restrict__ b1,
                           const float* __restrict__ W2, const float* __restrict__ b2,
                           float* __restrict__ dout, int M, int rf, int N) {
    // restore zero-invariants for the next launch (graph replay safe)
    int tid = blockIdx.x * blockDim.x + threadIdx.x;
    for (int z = tid; z < N; z += gridDim.x * blockDim.x) g_degc[z] = 0;
    for (int z = tid; z < NBM; z += gridDim.x * blockDim.x) { g_bm1[z] = 0u; g_bm2[z] = 0u; }
    for (int z = tid; z < NSCB; z += gridDim.x * blockDim.x) g_blk_state[z] = 0ull;
    if (tid == 0) { g_n1 = 0; g_n2 = 0; g_np = 0; }

    __shared__ float sh[4][64];
    __shared__ float sz[4][32];
    const int w = threadIdx.x >> 5, lane = threadIdx.x & 31;
    const int m = blockIdx.x * 4 + w;
    if (m >= M) return;
    const int v = idx[m];

    float h0 = fmaxf(g_out[(size_t)v * HID + lane]      + bias2[lane],      0.f);
    float h1 = fmaxf(g_out[(size_t)v * HID + 32 + lane] + bias2[32 + lane], 0.f);
    sh[w][lane] = h0; sh[w][32 + lane] = h1;
    __syncwarp();

    int k = v / rf;
    float y0 = y[2 * k], y1 = y[2 * k + 1];
    float q0 = fmaxf(y0 * W0[0] + y1 * W0[2] + b0[0], 0.f);
    float q1 = fmaxf(y0 * W0[1] + y1 * W0[3] + b0[1], 0.f);

    float z = b1[lane];
    #pragma unroll
    for (int j = 0; j < 64; ++j) z += sh[w][j] * W1[j * 32 + lane];
    z += q0 * W1[64 * 32 + lane] + q1 * W1[65 * 32 + lane];
    z = fmaxf(z, 0.f);
    sz[w][lane] = z;
    __syncwarp();

    float o = b2[lane];
    #pragma unroll
    for (int j = 0; j < 32; ++j) o += sz[w][j] * W2[j * 32 + lane];
    dout[m * 32 + lane] = o;
}

// ---------------- launch ------------------------------------------------------
extern "C" void kernel_launch(void* const* d_in, const int* in_sizes, int n_in,
                              void* d_out, int out_size) {
    const float* x    = (const float*)d_in[0];
    const float* ea   = (const float*)d_in[1];
    const float* y    = (const float*)d_in[2];
    const float* Wl1  = (const float*)d_in[3];
    const float* bl1  = (const float*)d_in[4];
    const float* Wr1  = (const float*)d_in[5];
    const float* br1  = (const float*)d_in[6];
    const float* We1  = (const float*)d_in[7];
    const float* att1 = (const float*)d_in[8];
    const float* bias1= (const float*)d_in[9];
    const float* Wl2  = (const float*)d_in[10];
    const float* bl2  = (const float*)d_in[11];
    const float* Wr2  = (const float*)d_in[12];
    const float* br2  = (const float*)d_in[13];
    const float* We2  = (const float*)d_in[14];
    const float* att2 = (const float*)d_in[15];
    const float* bias2= (const float*)d_in[16];
    const float* W0   = (const float*)d_in[17];
    const float* b0   = (const float*)d_in[18];
    const float* W1   = (const float*)d_in[19];
    const float* b1   = (const float*)d_in[20];
    const float* W2   = (const float*)d_in[21];
    const float* b2   = (const float*)d_in[22];
    const int*   ei   = (const int*)  d_in[23];
    const int*   nidx = (const int*)  d_in[24];

    const int N    = in_sizes[0] / FN;
    const int E    = in_sizes[23] / 2;
    const int M    = in_sizes[24];
    const int NG   = in_sizes[2] / 2;
    const int rf   = N / NG;

    const int EBLK = (E + 255) / 256;
    const int NB1K = (N + 1023) / 1024;
    const int LINB = (N + 127) / 128;

    // ---- active sets (bitmask probes) ----
    mark2_kernel   <<<(M + 255) / 256, 256>>>(nidx, M);
    markS_kernel   <<<EBLK, 256>>>(ei, E);

    // ---- compact CSR over T1 (one E-scan + single-pass lookback scan) ----
    collect_kernel <<<EBLK, 256>>>(ei, E);
    scan_lb_kernel <<<NB1K, 1024>>>();
    place_kernel   <<<1024, 256>>>(ea);
    prep_kernel    <<<512, 256>>>();

    // ---- layer 1: xl over all N + xr over T1 in ONE launch; fused edges ----
    lin_dual_kernel<FN, 0, 1, false><<<2 * LINB, 256>>>(x, Wl1, bl1, Wr1, br1, nullptr, N, LINB);
    edge_fused_kernel<<<1024, 256>>>(We1, att1, 1);

    // ---- layer 2: xl over T1 + xr over T2 in ONE launch; fused edges ----
    lin_dual_kernel<HID, 1, 2, true><<<2 * LINB, 256>>>(x, Wl2, bl2, Wr2, br2, bias1, N, LINB);
    edge_fused_kernel<<<128, 256>>>(We2, att2, 2);

    // ---- final MLP at node_idx (also restores zero-invariants) ----
    fin_kernel<<<512, 128>>>(nidx, bias2, y, W0, b0, W1, b1, W2, b2,
                             (float*)d_out, M, rf, N);
}

// round 17
// speedup vs baseline: 1.2412x; 1.0839x over previous
#include <cuda_runtime.h>
#include <cuda_fp16.h>
#include <cstddef>

typedef unsigned long long ull;
typedef unsigned int uint;

// ---------------- problem constants (shapes fixed by the dataset) -----------
#define MAXN 100000
#define MAXE 1600000
#define MAXET (MAXE + MAXN)
#define MAXETP (MAXET + 16)   // padded: slot MAXET is a never-written zero row
#define NBM  ((MAXN + 31) / 32)
#define NSCB 128              // scan lookback state slots (>= grid blocks)
#define FN   128     // node feature dim (layer1 input)
#define FE   32      // edge feature dim
#define HID  64

// ---------------- device scratch (static: no allocation allowed) ------------
__device__ __align__(16) __half g_xlh[MAXN * HID];  // source-side transform (fp16)
__device__ __align__(16) __half g_xrh[MAXN * HID];  // target-side transform (fp16)
__device__ float  g_out [MAXN * HID];       // layer output (valid at T1 nodes)
__device__ int    g_degc[MAXN];             // degree per T1 index (zero at entry)
__device__ int    g_mark1[MAXN];            // T1 index+1 (valid only where bm1 set)
__device__ uint   g_bm1 [NBM];              // T1 bitmask (zeroed by fin)
__device__ uint   g_bm2 [NBM];              // T2 bitmask (zeroed by fin)
__device__ int    g_rowptr[MAXN + 1];       // compact rowptr over T1 indices
__device__ int    g_cur [MAXN];
__device__ ull    g_blk_state[NSCB];        // lookback: (flag<<32)|value, zero at entry
__device__ int    g_csr_src[MAXETP];        // src node per compact slot
__device__ int    g_list1[MAXN];            // compacted T1 node list
__device__ int    g_list2[MAXN];            // compacted T2 node list
__device__ int2   g_pair_es[MAXET];         // (eid, src) of accepted edges
__device__ int2   g_pair_md[MAXET];         // (T1 idx, dst) of accepted edges
__device__ int    g_n1, g_n2, g_np;         // zero at entry (fin restores)
__device__ __align__(16) __half g_eap[(size_t)MAXETP * FE];  // permuted fp16 edge attrs

// ---------------- small helpers ---------------------------------------------
__device__ __forceinline__ void mma_f16(float acc[4], uint a0, uint a1, uint a2, uint a3,
                                        uint b0, uint b1) {
    asm volatile(
        "mma.sync.aligned.m16n8k16.row.col.f32.f16.f16.f32 "
        "{%0,%1,%2,%3}, {%4,%5,%6,%7}, {%8,%9}, {%0,%1,%2,%3};"
        : "+f"(acc[0]), "+f"(acc[1]), "+f"(acc[2]), "+f"(acc[3])
        : "r"(a0), "r"(a1), "r"(a2), "r"(a3), "r"(b0), "r"(b1));
}
__device__ __forceinline__ float2 h2f2(uint v) {
    __half2 h = *reinterpret_cast<__half2*>(&v);
    return __half22float2(h);
}
__device__ __forceinline__ uint f2h2(float x, float y) {
    __half2 h = __floats2half2_rn(x, y);
    return *reinterpret_cast<uint*>(&h);
}
__device__ __forceinline__ bool bm_test(const uint* bm, int i) {
    return (bm[i >> 5] >> (i & 31)) & 1u;
}

// ================= active-set construction ===================================
__global__ void mark2_kernel(const int* __restrict__ nidx, int M) {
    int m = blockIdx.x * blockDim.x + threadIdx.x;
    if (m >= M) return;
    int d = nidx[m];
    uint bit = 1u << (d & 31);
    if (!(atomicOr(&g_bm2[d >> 5], bit) & bit)) {
        int p = atomicAdd(&g_n2, 1); g_list2[p] = d;
    }
    if (!(atomicOr(&g_bm1[d >> 5], bit) & bit)) {
        int p = atomicAdd(&g_n1, 1); g_list1[p] = d; g_mark1[d] = p + 1;
    }
}

// T1 += sources of edges whose dst is in T2 (bit probe, L1-resident bitmask)
__global__ void markS_kernel(const int* __restrict__ ei, int E) {
    int i = blockIdx.x * blockDim.x + threadIdx.x;
    if (i >= E) return;
    int d = ei[E + i];
    if (bm_test(g_bm2, d)) {
        int s = ei[i];
        uint bit = 1u << (s & 31);
        if (!(atomicOr(&g_bm1[s >> 5], bit) & bit)) {
            int p = atomicAdd(&g_n1, 1); g_list1[p] = s; g_mark1[s] = p + 1;
        }
    }
}

// ================= compact CSR build (T1 segments only) =======================
// Single E-scan: bit probe, warp-aggregated append, degree count.
__global__ void collect_kernel(const int* __restrict__ ei, int E) {
    int i = blockIdx.x * blockDim.x + threadIdx.x;
    bool acc = false;
    int d = 0, m = 0;
    if (i < E) {
        d = ei[E + i];
        acc = bm_test(g_bm1, d);
    }
    uint mask = __ballot_sync(0xffffffffu, acc);
    if (!mask) return;
    int lane = threadIdx.x & 31;
    int base;
    if (lane == __ffs(mask) - 1) base = atomicAdd(&g_np, __popc(mask));
    base = __shfl_sync(0xffffffffu, base, __ffs(mask) - 1);
    if (acc) {
        int j = base + __popc(mask & ((1u << lane) - 1u));
        m = g_mark1[d] - 1;
        g_pair_es[j] = make_int2(i, ei[i]);
        g_pair_md[j] = make_int2(m, d);
        atomicAdd(&g_degc[m], 1);
    }
}

// single-pass decoupled-lookback scan; EMPTY blocks exit before the protocol.
__global__ __launch_bounds__(1024) void scan_lb_kernel() {
    __shared__ int wsum[32];
    __shared__ int s_excl;
    const int n1 = g_n1;
    const int bid = blockIdx.x;
    if (bid * 1024 >= n1) return;            // beyond last non-empty block: no one looks here
    const int i = bid * 1024 + threadIdx.x;
    const int lane = threadIdx.x & 31, wid = threadIdx.x >> 5;
    const bool lastblk = ((bid + 1) * 1024 >= n1);

    int v = (i < n1) ? (g_degc[i] + 1) : 0;
    int s = v;
    #pragma unroll
    for (int off = 1; off < 32; off <<= 1) {
        int t = __shfl_up_sync(0xffffffffu, s, off);
        if (lane >= off) s += t;
    }
    if (lane == 31) wsum[wid] = s;
    __syncthreads();
    if (wid == 0) {
        int ws = wsum[lane];
        #pragma unroll
        for (int off = 1; off < 32; off <<= 1) {
            int t = __shfl_up_sync(0xffffffffu, ws, off);
            if (lane >= off) ws += t;
        }
        wsum[lane] = ws;
    }
    __syncthreads();
    const int excl_in_blk = s - v + (wid ? wsum[wid - 1] : 0);
    const int block_total = wsum[31];

    if (threadIdx.x == 0) {
        int excl = 0;
        if (bid == 0) {
            atomicExch(&g_blk_state[0], ((ull)2 << 32) | (uint)block_total);
        } else {
            atomicExch(&g_blk_state[bid], ((ull)1 << 32) | (uint)block_total);
            int j = bid - 1;
            while (true) {
                ull st;
                do { st = atomicOr(&g_blk_state[j], 0ull); } while ((st >> 32) == 0);
                excl += (int)(st & 0xffffffffu);
                if ((st >> 32) == 2) break;
                --j;
            }
            atomicExch(&g_blk_state[bid], ((ull)2 << 32) | (uint)(excl + block_total));
        }
        s_excl = excl;
        if (lastblk) g_rowptr[n1] = excl + block_total;
    }
    __syncthreads();
    if (i < n1) {
        int rp = s_excl + excl_in_blk;
        g_rowptr[i] = rp;
        g_cur[i]    = rp;
    }
}

// place accepted edges into compact slots + permute/convert edge attrs
__global__ void place_kernel(const float* __restrict__ ea) {
    const int np = g_np;
    const int stride = gridDim.x * blockDim.x;
    for (int j = blockIdx.x * blockDim.x + threadIdx.x; j < np; j += stride) {
        int2 es = g_pair_es[j];
        int2 md = g_pair_md[j];
        int pos = atomicAdd(&g_cur[md.x], 1);
        g_csr_src[pos] = es.y;
        const float4* r4 = reinterpret_cast<const float4*>(ea) + (size_t)es.x * 8;
        __half2* dst = reinterpret_cast<__half2*>(g_eap + (size_t)pos * FE);
        #pragma unroll
        for (int q = 0; q < 8; ++q) {
            float4 v = r4[q];
            dst[2 * q]     = __floats2half2_rn(v.x, v.y);
            dst[2 * q + 1] = __floats2half2_rn(v.z, v.w);
        }
    }
}

// self-loop mean body (fills last slot of each T1 segment); gw over nprep*8 warps
__device__ __forceinline__ void prep_body(int blk, int nblk) {
    const int lane = threadIdx.x & 31;
    const int gws = nblk * 8;
    const int n1 = g_n1;
    for (int widx = blk * 8 + ((int)threadIdx.x >> 5); widx < n1; widx += gws) {
        const int d = g_list1[widx];
        const int rp0 = g_rowptr[widx], rp1 = g_rowptr[widx + 1];
        const int last = rp1 - 1;            // self-loop slot
        float s = 0.f;
        int e = rp0;
        for (; e + 4 <= last; e += 4) {
            float a0 = __half2float(g_eap[(size_t)(e + 0) * FE + lane]);
            float a1 = __half2float(g_eap[(size_t)(e + 1) * FE + lane]);
            float a2 = __half2float(g_eap[(size_t)(e + 2) * FE + lane]);
            float a3 = __half2float(g_eap[(size_t)(e + 3) * FE + lane]);
            s += (a0 + a1) + (a2 + a3);
        }
        for (; e < last; ++e) s += __half2float(g_eap[(size_t)e * FE + lane]);
        float mean = s / (float)max(last - rp0, 1);
        g_eap[(size_t)last * FE + lane] = __float2half_rn(mean);
        if (lane == 0) g_csr_src[last] = d;
    }
}

// ---------------- single-output node linear body (fp16 tensor MMA) -----------
template<int IN, int SET, bool HPREV>
__device__ __forceinline__ void lin_body(
        const float* __restrict__ inp, const float* __restrict__ W,
        const float* __restrict__ bias, const float* __restrict__ prevBias,
        int N, int right, int blk) {
    const int nlim = (SET == 0) ? N : (SET == 1 ? g_n1 : g_n2);
    const int nb = blk * 128;
    if (nb >= nlim) return;

    constexpr int KC = 16;
    __shared__ uint Xs[128][9];
    __shared__ uint Ws[8][68];

    const int t = threadIdx.x;
    const int lane = t & 31;
    const int mt = t >> 5;
    const int g = lane >> 2, c = lane & 3;

    float acc[8][4];
    #pragma unroll
    for (int nt = 0; nt < 8; ++nt) {
        acc[nt][0] = acc[nt][1] = acc[nt][2] = acc[nt][3] = 0.f;
    }

    for (int kc = 0; kc < IN; kc += KC) {
        __syncthreads();
        for (int idx = t; idx < 128 * 8; idx += 256) {
            int row = idx >> 3, kw = idx & 7;
            int m = nb + row;
            float v0 = 0.f, v1 = 0.f;
            if (m < nlim) {
                int node = (SET == 0) ? m : (SET == 1 ? g_list1[m] : g_list2[m]);
                int j = kc + 2 * kw;
                if (HPREV) {
                    float2 hv = *reinterpret_cast<const float2*>(g_out + (size_t)node * HID + j);
                    v0 = fmaxf(hv.x + prevBias[j], 0.f);
                    v1 = fmaxf(hv.y + prevBias[j + 1], 0.f);
                } else {
                    float2 xv = *reinterpret_cast<const float2*>(inp + (size_t)node * IN + j);
                    v0 = xv.x; v1 = xv.y;
                }
            }
            Xs[row][kw] = f2h2(v0, v1);
        }
        for (int idx = t; idx < 8 * 64; idx += 256) {
            int kw = idx >> 6, col = idx & 63;
            int k = kc + 2 * kw;
            Ws[kw][col] = f2h2(W[k * HID + col], W[(k + 1) * HID + col]);
        }
        __syncthreads();
        uint a0 = Xs[mt * 16 + g    ][c];
        uint a1 = Xs[mt * 16 + g + 8][c];
        uint a2 = Xs[mt * 16 + g    ][c + 4];
        uint a3 = Xs[mt * 16 + g + 8][c + 4];
        #pragma unroll
        for (int nt = 0; nt < 8; ++nt) {
            int col = nt * 8 + g;
            mma_f16(acc[nt], a0, a1, a2, a3, Ws[c][col], Ws[c + 4][col]);
        }
    }

    uint* dsth = reinterpret_cast<uint*>(right ? g_xrh : g_xlh);
    const int m0 = nb + mt * 16 + g;
    const int m1 = m0 + 8;
    const int node0 = (m0 < nlim) ? ((SET == 0) ? m0 : (SET == 1 ? g_list1[m0] : g_list2[m0])) : -1;
    const int node1 = (m1 < nlim) ? ((SET == 0) ? m1 : (SET == 1 ? g_list1[m1] : g_list2[m1])) : -1;
    #pragma unroll
    for (int nt = 0; nt < 8; ++nt) {
        int colL = nt * 8 + 2 * c;
        float bx = bias[colL], by = bias[colL + 1];
        if (node0 >= 0)
            dsth[(size_t)node0 * 32 + nt * 4 + c] = f2h2(acc[nt][0] + bx, acc[nt][1] + by);
        if (node1 >= 0)
            dsth[(size_t)node1 * 32 + nt * 4 + c] = f2h2(acc[nt][2] + bx, acc[nt][3] + by);
    }
}

// dual-output launch (+ optional prep range): blocks [0,nblkA) -> xl,
// [nblkA, 2*nblkA) -> xr, [2*nblkA, 2*nblkA+nprep) -> self-loop prep.
template<int IN, int SETA, int SETB, bool HPREV>
__global__ __launch_bounds__(256) void lin_dual_kernel(
        const float* __restrict__ inp,
        const float* __restrict__ WA, const float* __restrict__ bA,
        const float* __restrict__ WB, const float* __restrict__ bB,
        const float* __restrict__ prevBias, int N, int nblkA, int nprep) {
    const int b = (int)blockIdx.x;
    if (b < nblkA)
        lin_body<IN, SETA, HPREV>(inp, WA, bA, prevBias, N, 0, b);
    else if (b < 2 * nblkA)
        lin_body<IN, SETB, HPREV>(inp, WB, bB, prevBias, N, 1, b - nblkA);
    else
        prep_body(b - 2 * nblkA, nprep);
}

// ---------------- fused edge pass: warp-per-segment GATv2 --------------------
__global__ __launch_bounds__(256) void edge_fused_kernel(
        const float* __restrict__ We, const float* __restrict__ att, int layer) {
    const int n = (layer == 1) ? g_n1 : g_n2;
    const int t = threadIdx.x;
    const int lane = t & 31;
    const int g = lane >> 2;                 // row group 0..7
    const int c = lane & 3;                  // col-in-group 0..3
    const int gws = gridDim.x * 8;

    // preload B fragments (We as fp16) and att pairs into registers
    uint breg[8][2][2];
    float2 areg[8];
    #pragma unroll
    for (int nt = 0; nt < 8; ++nt) {
        const int nn = nt * 8 + g;
        #pragma unroll
        for (int ks = 0; ks < 2; ++ks) {
            int k0 = ks * 16 + 2 * c;
            breg[nt][ks][0] = f2h2(We[k0 * HID + nn],       We[(k0 + 1) * HID + nn]);
            breg[nt][ks][1] = f2h2(We[(k0 + 8) * HID + nn], We[(k0 + 9) * HID + nn]);
        }
        areg[nt] = reinterpret_cast<const float2*>(att)[nt * 4 + c];
    }

    const uint* xlh = reinterpret_cast<const uint*>(g_xlh);
    const uint* xrh = reinterpret_cast<const uint*>(g_xrh);

    for (int widx = blockIdx.x * 8 + (t >> 5); widx < n; widx += gws) {
        int d, m;
        if (layer == 1) { d = g_list1[widx]; m = widx; }
        else            { d = g_list2[widx]; m = g_mark1[d] - 1; }
        const int rp0 = g_rowptr[m], rp1 = g_rowptr[m + 1];

        // xr[d] loaded once per segment
        float2 xr[8];
        #pragma unroll
        for (int nt = 0; nt < 8; ++nt)
            xr[nt] = h2f2(xrh[(size_t)d * 32 + nt * 4 + c]);

        float den = 0.f;
        float2 o[8];
        #pragma unroll
        for (int nt = 0; nt < 8; ++nt) o[nt] = make_float2(0.f, 0.f);

        for (int base = rp0; base < rp1; base += 16) {
            const int rowA = base + g;
            const int rowB = rowA + 8;
            const bool vA = rowA < rp1, vB = rowB < rp1;
            const int slotA = vA ? rowA : MAXET;   // pad slot: zeros
            const int slotB = vB ? rowB : MAXET;
            const int sA = g_csr_src[slotA], sB = g_csr_src[slotB];
            const uint* pA = reinterpret_cast<const uint*>(g_eap + (size_t)slotA * FE);
            const uint* pB = reinterpret_cast<const uint*>(g_eap + (size_t)slotB * FE);

            uint afr[2][4];
            #pragma unroll
            for (int ks = 0; ks < 2; ++ks) {
                afr[ks][0] = pA[ks * 8 + c];
                afr[ks][1] = pB[ks * 8 + c];
                afr[ks][2] = pA[ks * 8 + c + 4];
                afr[ks][3] = pB[ks * 8 + c + 4];
            }

            float2 xlA[8], xlB[8];
            float partA = 0.f, partB = 0.f;
            #pragma unroll
            for (int nt = 0; nt < 8; ++nt) {
                float acc[4] = {0.f, 0.f, 0.f, 0.f};
                mma_f16(acc, afr[0][0], afr[0][1], afr[0][2], afr[0][3],
                        breg[nt][0][0], breg[nt][0][1]);
                mma_f16(acc, afr[1][0], afr[1][1], afr[1][2], afr[1][3],
                        breg[nt][1][0], breg[nt][1][1]);
                xlA[nt] = h2f2(xlh[(size_t)sA * 32 + nt * 4 + c]);
                xlB[nt] = h2f2(xlh[(size_t)sB * 32 + nt * 4 + c]);
                float u0 = acc[0] + xlA[nt].x + xr[nt].x;
                float u1 = acc[1] + xlA[nt].y + xr[nt].y;
                float u2 = acc[2] + xlB[nt].x + xr[nt].x;
                float u3 = acc[3] + xlB[nt].y + xr[nt].y;
                u0 = fmaxf(u0, 0.f) + 0.2f * fminf(u0, 0.f);
                u1 = fmaxf(u1, 0.f) + 0.2f * fminf(u1, 0.f);
                u2 = fmaxf(u2, 0.f) + 0.2f * fminf(u2, 0.f);
                u3 = fmaxf(u3, 0.f) + 0.2f * fminf(u3, 0.f);
                partA = fmaf(u0, areg[nt].x, fmaf(u1, areg[nt].y, partA));
                partB = fmaf(u2, areg[nt].x, fmaf(u3, areg[nt].y, partB));
            }
            partA += __shfl_xor_sync(0xffffffffu, partA, 1);
            partA += __shfl_xor_sync(0xffffffffu, partA, 2);
            partB += __shfl_xor_sync(0xffffffffu, partB, 1);
            partB += __shfl_xor_sync(0xffffffffu, partB, 2);
            const float eA = vA ? __expf(partA) : 0.f;
            const float eB = vB ? __expf(partB) : 0.f;
            den += eA + eB;
            #pragma unroll
            for (int nt = 0; nt < 8; ++nt) {
                o[nt].x = fmaf(eA, xlA[nt].x, fmaf(eB, xlB[nt].x, o[nt].x));
                o[nt].y = fmaf(eA, xlA[nt].y, fmaf(eB, xlB[nt].y, o[nt].y));
            }
        }

        // reduce across the 8 row-groups (lane = g*4 + c)
        #pragma unroll
        for (int off = 4; off <= 16; off <<= 1) {
            den += __shfl_xor_sync(0xffffffffu, den, off);
            #pragma unroll
            for (int nt = 0; nt < 8; ++nt) {
                o[nt].x += __shfl_xor_sync(0xffffffffu, o[nt].x, off);
                o[nt].y += __shfl_xor_sync(0xffffffffu, o[nt].y, off);
            }
        }
        const float inv = 1.f / den;
        if (g == 0) {
            float2* out2 = reinterpret_cast<float2*>(g_out);
            #pragma unroll
            for (int nt = 0; nt < 8; ++nt)
                out2[(size_t)d * 32 + nt * 4 + c] = make_float2(o[nt].x * inv, o[nt].y * inv);
        }
    }
}

// ---------------- final MLP at node_idx + restore zero-invariants ------------
__global__ void fin_kernel(const int* __restrict__ idx, const float* __restrict__ bias2,
                           const float* __restrict__ y,
                           const float* __restrict__ W0, const float* __restrict__ b0,
                           const float* __restrict__ W1, const float* __restrict__ b1,
                           const float* __restrict__ W2, const float* __restrict__ b2,
                           float* __restrict__ dout, int M, int rf, int N) {
    // restore zero-invariants for the next launch (graph replay safe)
    int tid = blockIdx.x * blockDim.x + threadIdx.x;
    for (int z = tid; z < N; z += gridDim.x * blockDim.x) g_degc[z] = 0;
    for (int z = tid; z < NBM; z += gridDim.x * blockDim.x) { g_bm1[z] = 0u; g_bm2[z] = 0u; }
    for (int z = tid; z < NSCB; z += gridDim.x * blockDim.x) g_blk_state[z] = 0ull;
    if (tid == 0) { g_n1 = 0; g_n2 = 0; g_np = 0; }

    __shared__ float sh[4][64];
    __shared__ float sz[4][32];
    const int w = threadIdx.x >> 5, lane = threadIdx.x & 31;
    const int m = blockIdx.x * 4 + w;
    if (m >= M) return;
    const int v = idx[m];

    float h0 = fmaxf(g_out[(size_t)v * HID + lane]      + bias2[lane],      0.f);
    float h1 = fmaxf(g_out[(size_t)v * HID + 32 + lane] + bias2[32 + lane], 0.f);
    sh[w][lane] = h0; sh[w][32 + lane] = h1;
    __syncwarp();

    int k = v / rf;
    float y0 = y[2 * k], y1 = y[2 * k + 1];
    float q0 = fmaxf(y0 * W0[0] + y1 * W0[2] + b0[0], 0.f);
    float q1 = fmaxf(y0 * W0[1] + y1 * W0[3] + b0[1], 0.f);

    float z = b1[lane];
    #pragma unroll
    for (int j = 0; j < 64; ++j) z += sh[w][j] * W1[j * 32 + lane];
    z += q0 * W1[64 * 32 + lane] + q1 * W1[65 * 32 + lane];
    z = fmaxf(z, 0.f);
    sz[w][lane] = z;
    __syncwarp();

    float o = b2[lane];
    #pragma unroll
    for (int j = 0; j < 32; ++j) o += sz[w][j] * W2[j * 32 + lane];
    dout[m * 32 + lane] = o;
}

// ---------------- launch ------------------------------------------------------
extern "C" void kernel_launch(void* const* d_in, const int* in_sizes, int n_in,
                              void* d_out, int out_size) {
    const float* x    = (const float*)d_in[0];
    const float* ea   = (const float*)d_in[1];
    const float* y    = (const float*)d_in[2];
    const float* Wl1  = (const float*)d_in[3];
    const float* bl1  = (const float*)d_in[4];
    const float* Wr1  = (const float*)d_in[5];
    const float* br1  = (const float*)d_in[6];
    const float* We1  = (const float*)d_in[7];
    const float* att1 = (const float*)d_in[8];
    const float* bias1= (const float*)d_in[9];
    const float* Wl2  = (const float*)d_in[10];
    const float* bl2  = (const float*)d_in[11];
    const float* Wr2  = (const float*)d_in[12];
    const float* br2  = (const float*)d_in[13];
    const float* We2  = (const float*)d_in[14];
    const float* att2 = (const float*)d_in[15];
    const float* bias2= (const float*)d_in[16];
    const float* W0   = (const float*)d_in[17];
    const float* b0   = (const float*)d_in[18];
    const float* W1   = (const float*)d_in[19];
    const float* b1   = (const float*)d_in[20];
    const float* W2   = (const float*)d_in[21];
    const float* b2   = (const float*)d_in[22];
    const int*   ei   = (const int*)  d_in[23];
    const int*   nidx = (const int*)  d_in[24];

    const int N    = in_sizes[0] / FN;
    const int E    = in_sizes[23] / 2;
    const int M    = in_sizes[24];
    const int NG   = in_sizes[2] / 2;
    const int rf   = N / NG;

    const int EBLK = (E + 255) / 256;
    const int NB1K = (N + 1023) / 1024;
    const int LINB = (N + 127) / 128;
    const int PREPB = 256;

    // ---- active sets (bitmask probes) ----
    mark2_kernel   <<<(M + 255) / 256, 256>>>(nidx, M);
    markS_kernel   <<<EBLK, 256>>>(ei, E);

    // ---- compact CSR over T1 (one E-scan + single-pass lookback scan) ----
    collect_kernel <<<EBLK, 256>>>(ei, E);
    scan_lb_kernel <<<NB1K, 1024>>>();
    place_kernel   <<<1024, 256>>>(ea);

    // ---- layer 1: xl(all N) + xr(T1) + self-loop prep in ONE launch ----
    lin_dual_kernel<FN, 0, 1, false><<<2 * LINB + PREPB, 256>>>(
        x, Wl1, bl1, Wr1, br1, nullptr, N, LINB, PREPB);
    edge_fused_kernel<<<1024, 256>>>(We1, att1, 1);

    // ---- layer 2: xl over T1 + xr over T2 in ONE launch; fused edges ----
    lin_dual_kernel<HID, 1, 2, true><<<2 * LINB, 256>>>(
        x, Wl2, bl2, Wr2, br2, bias1, N, LINB, 0);
    edge_fused_kernel<<<128, 256>>>(We2, att2, 2);

    // ---- final MLP at node_idx (also restores zero-invariants) ----
    fin_kernel<<<512, 128>>>(nidx, bias2, y, W0, b0, W1, b1, W2, b2,
                             (float*)d_out, M, rf, N);
}